// round 1
// baseline (speedup 1.0000x reference)
#include <cuda_runtime.h>
#include <math.h>

#define S_LEN 577
#define BATCH 8
#define DIM   1024
#define NHEAD 16
#define HD    64
#define NBOX  16
#define NROWS (S_LEN*BATCH)   /* 4616 */
#define MROW  136             /* 128 mask rows + 8 cls rows */

/* ------------------------------------------------------------------ */
/* scratch (device globals; no allocation allowed)                    */
/* ------------------------------------------------------------------ */
__device__ float g_h[NROWS*DIM];          // LN1 output
__device__ float g_kv[NROWS*2048];        // [row, 0:1024]=k, [1024:2048]=v
__device__ float g_q0[BATCH*DIM];         // q for CLS token
__device__ float g_attn[BATCH*NHEAD*S_LEN];
__device__ float g_attout[MROW*DIM];      // attention output pre-proj
__device__ float g_proj[MROW*DIM];        // after out_w
__device__ float g_resid[MROW*DIM];
__device__ float g_t[MROW*DIM];           // LN2 output
__device__ float g_fc[MROW*4096];
__device__ float g_mlp[MROW*DIM];

/* ------------------------------------------------------------------ */
__device__ __forceinline__ float block_reduce(float v, float* sm, bool is_max) {
    int lane = threadIdx.x & 31, wid = threadIdx.x >> 5;
    #pragma unroll
    for (int o = 16; o; o >>= 1) {
        float u = __shfl_down_sync(0xffffffffu, v, o);
        v = is_max ? fmaxf(v, u) : v + u;
    }
    if (lane == 0) sm[wid] = v;
    __syncthreads();
    int nw = blockDim.x >> 5;
    if (wid == 0) {
        v = (lane < nw) ? sm[lane] : (is_max ? -3.0e38f : 0.0f);
        #pragma unroll
        for (int o = 16; o; o >>= 1) {
            float u = __shfl_down_sync(0xffffffffu, v, o);
            v = is_max ? fmaxf(v, u) : v + u;
        }
        if (lane == 0) sm[0] = v;
    }
    __syncthreads();
    float r = sm[0];
    __syncthreads();
    return r;
}

/* ------------------------------------------------------------------ */
/* LayerNorm over 1024 cols, one block (256 thr) per row              */
/* ------------------------------------------------------------------ */
__global__ void ln1_kernel(const float* __restrict__ x,
                           const float* __restrict__ g,
                           const float* __restrict__ b,
                           float* __restrict__ out) {
    __shared__ float sred[32];
    int row = blockIdx.x, t = threadIdx.x;
    float4 v = ((const float4*)(x + (size_t)row*DIM))[t];
    float s = v.x + v.y + v.z + v.w;
    s = block_reduce(s, sred, false);
    float mean = s * (1.0f/DIM);
    float dx = v.x-mean, dy = v.y-mean, dz = v.z-mean, dw = v.w-mean;
    float ss = dx*dx + dy*dy + dz*dz + dw*dw;
    ss = block_reduce(ss, sred, false);
    float inv = rsqrtf(ss*(1.0f/DIM) + 1e-5f);
    float4 gv = ((const float4*)g)[t];
    float4 bv = ((const float4*)b)[t];
    float4 o;
    o.x = dx*inv*gv.x + bv.x;  o.y = dy*inv*gv.y + bv.y;
    o.z = dz*inv*gv.z + bv.z;  o.w = dw*inv*gv.w + bv.w;
    ((float4*)(out + (size_t)row*DIM))[t] = o;
}

/* ------------------------------------------------------------------ */
/* C[m,n] = dot(A[m,:], W[n,:]) + bias[n]  (both K-major)             */
/* 128x128 tile, BK=8, 256 threads, 8x8 per thread.                   */
/* N, K multiples of 128/8; M ragged (guarded).                       */
/* ACT: 0 = none, 1 = QuickGELU                                       */
/* ------------------------------------------------------------------ */
template<int ACT>
__global__ void gemm_kernel(const float* __restrict__ A,
                            const float* __restrict__ W,
                            const float* __restrict__ bias,
                            float* __restrict__ C,
                            int M, int N, int K) {
    __shared__ float As[8][128];
    __shared__ float Ws[8][128];
    int tid = threadIdx.x;
    int tx = tid & 15, ty = tid >> 4;
    int m0 = blockIdx.y * 128, n0 = blockIdx.x * 128;
    int lr = tid >> 1;            // 0..127 tile row for loads
    int lk = (tid & 1) * 4;       // 0 or 4
    float acc[8][8];
    #pragma unroll
    for (int i = 0; i < 8; i++)
        #pragma unroll
        for (int j = 0; j < 8; j++) acc[i][j] = 0.0f;

    for (int k0 = 0; k0 < K; k0 += 8) {
        float4 av = make_float4(0.f, 0.f, 0.f, 0.f);
        int am = m0 + lr;
        if (am < M) av = *(const float4*)(A + (size_t)am*K + k0 + lk);
        As[lk+0][lr] = av.x; As[lk+1][lr] = av.y;
        As[lk+2][lr] = av.z; As[lk+3][lr] = av.w;
        float4 wv = *(const float4*)(W + (size_t)(n0 + lr)*K + k0 + lk);
        Ws[lk+0][lr] = wv.x; Ws[lk+1][lr] = wv.y;
        Ws[lk+2][lr] = wv.z; Ws[lk+3][lr] = wv.w;
        __syncthreads();
        #pragma unroll
        for (int k = 0; k < 8; k++) {
            float a[8], w[8];
            *(float4*)(a)     = *(const float4*)&As[k][ty*8];
            *(float4*)(a + 4) = *(const float4*)&As[k][ty*8 + 4];
            *(float4*)(w)     = *(const float4*)&Ws[k][tx*8];
            *(float4*)(w + 4) = *(const float4*)&Ws[k][tx*8 + 4];
            #pragma unroll
            for (int i = 0; i < 8; i++)
                #pragma unroll
                for (int j = 0; j < 8; j++)
                    acc[i][j] += a[i] * w[j];
        }
        __syncthreads();
    }

    #pragma unroll
    for (int i = 0; i < 8; i++) {
        int m = m0 + ty*8 + i;
        if (m >= M) continue;
        float* Cp = C + (size_t)m*N + n0 + tx*8;
        const float* bp = bias + n0 + tx*8;
        #pragma unroll
        for (int j = 0; j < 8; j++) {
            float v = acc[i][j] + bp[j];
            if (ACT == 1) v = v / (1.0f + expf(-1.702f * v));  // QuickGELU
            Cp[j] = v;
        }
    }
}

/* ------------------------------------------------------------------ */
/* attn[b,h,s] = (q0[b,h,:]/8) . k[s,b,h,:]                           */
/* ------------------------------------------------------------------ */
__global__ void attn_kernel() {
    int bh = blockIdx.x;               // 0..127
    int b = bh >> 4, h = bh & 15;
    __shared__ float q[HD];
    int t = threadIdx.x;               // 128 threads
    if (t < HD) q[t] = g_q0[b*DIM + h*HD + t] * 0.125f;
    __syncthreads();
    for (int s = t; s < S_LEN; s += 128) {
        const float4* kr = (const float4*)(g_kv + (size_t)(s*BATCH + b)*2048 + h*HD);
        float acc = 0.0f;
        #pragma unroll
        for (int i = 0; i < 16; i++) {
            float4 kv4 = kr[i];
            acc += kv4.x*q[i*4+0] + kv4.y*q[i*4+1] + kv4.z*q[i*4+2] + kv4.w*q[i*4+3];
        }
        g_attn[bh*S_LEN + s] = acc;
    }
}

/* ------------------------------------------------------------------ */
/* Per (b,h): 17 softmax variants (16 masked boxes + 1 plain), then   */
/* P[17,577] @ V[577,64] with V staged through SMEM (read once).      */
/* dyn smem: p 9812 | attn 580 | v 4096 | red 32 floats = 58080 B     */
/* ------------------------------------------------------------------ */
__global__ void softmax_av_kernel(const float* __restrict__ mask) {
    extern __shared__ float sm[];
    float* sm_p    = sm;               // 17*577 (padded region 9812)
    float* sm_attn = sm + 9812;        // 577 (padded 580)
    float* sm_v    = sm + 10392;       // 64*64, 16B aligned
    float* sm_red  = sm + 14488;       // 32
    int bh = blockIdx.x, b = bh >> 4, h = bh & 15;
    int t = threadIdx.x;               // 256

    for (int s = t; s < S_LEN; s += 256) sm_attn[s] = g_attn[bh*S_LEN + s];
    __syncthreads();

    for (int var = 0; var < 17; var++) {
        float* pr = sm_p + var * S_LEN;
        const float* mrow = (var < 16)
            ? (mask + (size_t)((b*NBOX + var)*NHEAD + h) * S_LEN) : (const float*)0;
        float mx = -3.0e38f;
        for (int s = t; s < S_LEN; s += 256) {
            float a = sm_attn[s] + (mrow ? mrow[s] : 0.0f);
            pr[s] = a;
            mx = fmaxf(mx, a);
        }
        mx = block_reduce(mx, sm_red, true);
        float sum = 0.0f;
        for (int s = t; s < S_LEN; s += 256) {
            float e = expf(pr[s] - mx);
            pr[s] = e;
            sum += e;
        }
        sum = block_reduce(sum, sm_red, false);
        float inv = 1.0f / sum;
        for (int s = t; s < S_LEN; s += 256) pr[s] *= inv;
        __syncthreads();
    }

    int e = t & 63, grp = t >> 6;      // grp uniform per warp
    float acc[5] = {0.f, 0.f, 0.f, 0.f, 0.f};
    for (int s0 = 0; s0 < S_LEN; s0 += 64) {
        __syncthreads();
        #pragma unroll
        for (int it = 0; it < 4; it++) {
            int idx = t + it * 256;           // 0..1023
            int r = idx >> 4, c4 = (idx & 15) << 2;
            int s = s0 + r;
            float4 vv = make_float4(0.f, 0.f, 0.f, 0.f);
            if (s < S_LEN)
                vv = *(const float4*)(g_kv + (size_t)(s*BATCH + b)*2048 + 1024 + h*HD + c4);
            *(float4*)(sm_v + r*64 + c4) = vv;
        }
        __syncthreads();
        int smax = min(64, S_LEN - s0);
        for (int r = 0; r < smax; r++) {
            float vv = sm_v[r*64 + e];
            #pragma unroll
            for (int i = 0; i < 4; i++)
                acc[i] += sm_p[(grp + 4*i)*S_LEN + s0 + r] * vv;
            if (grp == 0)
                acc[4] += sm_p[16*S_LEN + s0 + r] * vv;
        }
    }
    int col = h*HD + e;
    #pragma unroll
    for (int i = 0; i < 4; i++) {
        int var = grp + 4*i;
        g_attout[(size_t)(b*NBOX + var)*DIM + col] = acc[i];    // mask rows 0..127
    }
    if (grp == 0)
        g_attout[(size_t)(128 + b)*DIM + col] = acc[4];         // cls rows 128..135
}

/* ------------------------------------------------------------------ */
/* resid = x0 + proj; t = LN2(resid)                                  */
/* ------------------------------------------------------------------ */
__global__ void resid_ln2_kernel(const float* __restrict__ x,
                                 const float* __restrict__ g2,
                                 const float* __restrict__ b2) {
    __shared__ float sred[32];
    int m = blockIdx.x, t = threadIdx.x;
    int b = (m < 128) ? (m >> 4) : (m - 128);
    float4 xv = ((const float4*)(x      + (size_t)b*DIM))[t];   // x[0,b,:]
    float4 pv = ((const float4*)(g_proj + (size_t)m*DIM))[t];
    float4 r = make_float4(xv.x+pv.x, xv.y+pv.y, xv.z+pv.z, xv.w+pv.w);
    ((float4*)(g_resid + (size_t)m*DIM))[t] = r;
    float s = r.x + r.y + r.z + r.w;
    s = block_reduce(s, sred, false);
    float mean = s * (1.0f/DIM);
    float dx = r.x-mean, dy = r.y-mean, dz = r.z-mean, dw = r.w-mean;
    float ss = dx*dx + dy*dy + dz*dz + dw*dw;
    ss = block_reduce(ss, sred, false);
    float inv = rsqrtf(ss*(1.0f/DIM) + 1e-5f);
    float4 gv = ((const float4*)g2)[t];
    float4 bv = ((const float4*)b2)[t];
    float4 o;
    o.x = dx*inv*gv.x + bv.x;  o.y = dy*inv*gv.y + bv.y;
    o.z = dz*inv*gv.z + bv.z;  o.w = dw*inv*gv.w + bv.w;
    ((float4*)(g_t + (size_t)m*DIM))[t] = o;
}

/* ------------------------------------------------------------------ */
/* final = resid + mlp; scatter: rows 0..127 -> mask_cls, 128.. -> cls*/
/* ------------------------------------------------------------------ */
__global__ void final_kernel(float* __restrict__ out) {
    int m = blockIdx.x, t = threadIdx.x;
    float4 r  = ((const float4*)(g_resid + (size_t)m*DIM))[t];
    float4 mm = ((const float4*)(g_mlp   + (size_t)m*DIM))[t];
    float4 o = make_float4(r.x+mm.x, r.y+mm.y, r.z+mm.z, r.w+mm.w);
    float* dst = (m < 128) ? (out + (size_t)m*DIM)
                           : (out + 128*DIM + (size_t)(m-128)*DIM);
    ((float4*)dst)[t] = o;
}

/* ------------------------------------------------------------------ */
extern "C" void kernel_launch(void* const* d_in, const int* in_sizes, int n_in,
                              void* d_out, int out_size) {
    const float* x         = (const float*)d_in[0];
    const float* mask      = (const float*)d_in[1];
    /* d_in[2]=box_coords, d_in[3]=layers, d_in[4]=need_patch: unused */
    const float* in_proj_w = (const float*)d_in[5];
    const float* in_proj_b = (const float*)d_in[6];
    const float* out_w     = (const float*)d_in[7];
    const float* out_b     = (const float*)d_in[8];
    const float* ln1_g     = (const float*)d_in[9];
    const float* ln1_b     = (const float*)d_in[10];
    const float* ln2_g     = (const float*)d_in[11];
    const float* ln2_b     = (const float*)d_in[12];
    const float* fc_w      = (const float*)d_in[13];
    const float* fc_b      = (const float*)d_in[14];
    const float* proj_w    = (const float*)d_in[15];
    const float* proj_b    = (const float*)d_in[16];

    float *ph, *pkv, *pq0, *pattout, *pproj, *pt, *pfc, *pmlp;
    cudaGetSymbolAddress((void**)&ph,      g_h);
    cudaGetSymbolAddress((void**)&pkv,     g_kv);
    cudaGetSymbolAddress((void**)&pq0,     g_q0);
    cudaGetSymbolAddress((void**)&pattout, g_attout);
    cudaGetSymbolAddress((void**)&pproj,   g_proj);
    cudaGetSymbolAddress((void**)&pt,      g_t);
    cudaGetSymbolAddress((void**)&pfc,     g_fc);
    cudaGetSymbolAddress((void**)&pmlp,    g_mlp);

    /* 1. LN1 over all tokens */
    ln1_kernel<<<NROWS, 256>>>(x, ln1_g, ln1_b, ph);

    /* 2. K,V projection: [4616,1024] x [2048,1024]^T (dominant GEMM) */
    gemm_kernel<0><<<dim3(2048/128, (NROWS+127)/128), 256>>>(
        ph, in_proj_w + 1024*1024, in_proj_b + 1024, pkv, NROWS, 2048, 1024);

    /* 3. Q projection, CLS row only (rows 0..7 of g_h are s=0) */
    gemm_kernel<0><<<dim3(1024/128, 1), 256>>>(
        ph, in_proj_w, in_proj_b, pq0, BATCH, 1024, 1024);

    /* 4. attn logits */
    attn_kernel<<<BATCH*NHEAD, 128>>>();

    /* 5. 17-way softmax + P@V */
    cudaFuncSetAttribute(softmax_av_kernel,
                         cudaFuncAttributeMaxDynamicSharedMemorySize, 58080);
    softmax_av_kernel<<<BATCH*NHEAD, 256, 58080>>>(mask);

    /* 6. output projection (136 rows) */
    gemm_kernel<0><<<dim3(1024/128, 2), 256>>>(
        pattout, out_w, out_b, pproj, MROW, 1024, 1024);

    /* 7. residual + LN2 */
    resid_ln2_kernel<<<MROW, 256>>>(x, ln2_g, ln2_b);

    /* 8. MLP fc + QuickGELU */
    gemm_kernel<1><<<dim3(4096/128, 2), 256>>>(
        pt, fc_w, fc_b, pfc, MROW, 4096, 1024);

    /* 9. MLP proj */
    gemm_kernel<0><<<dim3(1024/128, 2), 256>>>(
        pfc, proj_w, proj_b, pmlp, MROW, 1024, 4096);

    /* 10. residual + scatter to output */
    final_kernel<<<MROW, 256>>>((float*)d_out);
}

// round 2
// speedup vs baseline: 2.1969x; 2.1969x over previous
#include <cuda_runtime.h>
#include <math.h>
#include <stdint.h>

#define S_LEN 577
#define BATCH 8
#define DIM   1024
#define NHEAD 16
#define HD    64
#define NBOX  16
#define NROWS (S_LEN*BATCH)   /* 4616 */
#define MROW  136             /* 128 mask rows + 8 cls rows */

/* ------------------------------------------------------------------ */
/* scratch (device globals; no allocation allowed)                    */
/* ------------------------------------------------------------------ */
__device__ float g_h[NROWS*DIM];          // LN1 output
__device__ float g_kv[NROWS*2048];        // [row, 0:1024]=k, [1024:2048]=v
__device__ float g_q0[BATCH*DIM];         // q for CLS token
__device__ float g_attn[BATCH*NHEAD*S_LEN];
__device__ float g_attout[MROW*DIM];      // attention output pre-proj
__device__ float g_proj[MROW*DIM];        // after out_w
__device__ float g_resid[MROW*DIM];
__device__ float g_t[MROW*DIM];           // LN2 output
__device__ float g_fc[MROW*4096];
__device__ float g_mlp[MROW*DIM];

/* ------------------------------------------------------------------ */
__device__ __forceinline__ float block_reduce(float v, float* sm, bool is_max) {
    int lane = threadIdx.x & 31, wid = threadIdx.x >> 5;
    #pragma unroll
    for (int o = 16; o; o >>= 1) {
        float u = __shfl_down_sync(0xffffffffu, v, o);
        v = is_max ? fmaxf(v, u) : v + u;
    }
    if (lane == 0) sm[wid] = v;
    __syncthreads();
    int nw = blockDim.x >> 5;
    if (wid == 0) {
        v = (lane < nw) ? sm[lane] : (is_max ? -3.0e38f : 0.0f);
        #pragma unroll
        for (int o = 16; o; o >>= 1) {
            float u = __shfl_down_sync(0xffffffffu, v, o);
            v = is_max ? fmaxf(v, u) : v + u;
        }
        if (lane == 0) sm[0] = v;
    }
    __syncthreads();
    float r = sm[0];
    __syncthreads();
    return r;
}

__device__ __forceinline__ uint32_t f2tf32(float f) {
    uint32_t u;
    asm("cvt.rna.tf32.f32 %0, %1;" : "=r"(u) : "f"(f));
    return u;
}

/* ------------------------------------------------------------------ */
/* LayerNorm over 1024 cols, one block (256 thr) per row              */
/* ------------------------------------------------------------------ */
__global__ void ln1_kernel(const float* __restrict__ x,
                           const float* __restrict__ g,
                           const float* __restrict__ b,
                           float* __restrict__ out) {
    __shared__ float sred[32];
    int row = blockIdx.x, t = threadIdx.x;
    float4 v = ((const float4*)(x + (size_t)row*DIM))[t];
    float s = v.x + v.y + v.z + v.w;
    s = block_reduce(s, sred, false);
    float mean = s * (1.0f/DIM);
    float dx = v.x-mean, dy = v.y-mean, dz = v.z-mean, dw = v.w-mean;
    float ss = dx*dx + dy*dy + dz*dz + dw*dw;
    ss = block_reduce(ss, sred, false);
    float inv = rsqrtf(ss*(1.0f/DIM) + 1e-5f);
    float4 gv = ((const float4*)g)[t];
    float4 bv = ((const float4*)b)[t];
    float4 o;
    o.x = dx*inv*gv.x + bv.x;  o.y = dy*inv*gv.y + bv.y;
    o.z = dz*inv*gv.z + bv.z;  o.w = dw*inv*gv.w + bv.w;
    ((float4*)(out + (size_t)row*DIM))[t] = o;
}

/* ------------------------------------------------------------------ */
/* Tensor-core tf32 GEMM: C[m,n] = dot(A[m,:], W[n,:]) + bias[n]      */
/* BM=BN=128, BK=32, 256 threads = 8 warps (2x4), warp tile 64x32,    */
/* mma.sync.m16n8k8.tf32, fp32 accumulate.                            */
/* N, K multiples of 128/32; M ragged (guarded).                      */
/* ACT: 0 = none, 1 = QuickGELU                                       */
/* ------------------------------------------------------------------ */
template<int ACT>
__global__ void gemm_tc(const float* __restrict__ A,
                        const float* __restrict__ W,
                        const float* __restrict__ bias,
                        float* __restrict__ C,
                        int M, int N, int K) {
    __shared__ uint32_t As[32][136];   // [k][m], tf32 bits
    __shared__ uint32_t Bs[32][136];   // [k][n], tf32 bits

    int tid = threadIdx.x;
    int warp = tid >> 5, lane = tid & 31;
    int wm = warp & 1, wn = warp >> 1;          // warp grid 2 (M) x 4 (N)
    int g = lane >> 2, c = lane & 3;            // groupID, thread-in-group
    int m0 = blockIdx.y * 128, n0 = blockIdx.x * 128;

    int lm = tid & 31;          // tile row/col handled by this loader thread
    int lkq = tid >> 5;         // k-quad 0..7

    float acc[4][4][4];
    #pragma unroll
    for (int i = 0; i < 4; i++)
        #pragma unroll
        for (int j = 0; j < 4; j++)
            #pragma unroll
            for (int r = 0; r < 4; r++) acc[i][j][r] = 0.0f;

    for (int k0 = 0; k0 < K; k0 += 32) {
        /* load A tile 128x32, B tile 128x32 (both K-major rows) */
        #pragma unroll
        for (int r = 0; r < 4; r++) {
            int m = r*32 + lm;
            float4 av = make_float4(0.f, 0.f, 0.f, 0.f);
            if (m0 + m < M)
                av = *(const float4*)(A + (size_t)(m0 + m)*K + k0 + lkq*4);
            As[lkq*4+0][m] = f2tf32(av.x);
            As[lkq*4+1][m] = f2tf32(av.y);
            As[lkq*4+2][m] = f2tf32(av.z);
            As[lkq*4+3][m] = f2tf32(av.w);
            float4 wv = *(const float4*)(W + (size_t)(n0 + m)*K + k0 + lkq*4);
            Bs[lkq*4+0][m] = f2tf32(wv.x);
            Bs[lkq*4+1][m] = f2tf32(wv.y);
            Bs[lkq*4+2][m] = f2tf32(wv.z);
            Bs[lkq*4+3][m] = f2tf32(wv.w);
        }
        __syncthreads();

        #pragma unroll
        for (int kk = 0; kk < 32; kk += 8) {
            uint32_t a[4][4];
            #pragma unroll
            for (int i = 0; i < 4; i++) {
                int mr = wm*64 + i*16 + g;
                a[i][0] = As[kk + c    ][mr    ];
                a[i][1] = As[kk + c    ][mr + 8];
                a[i][2] = As[kk + c + 4][mr    ];
                a[i][3] = As[kk + c + 4][mr + 8];
            }
            uint32_t b[4][2];
            #pragma unroll
            for (int j = 0; j < 4; j++) {
                int nc = wn*32 + j*8 + g;
                b[j][0] = Bs[kk + c    ][nc];
                b[j][1] = Bs[kk + c + 4][nc];
            }
            #pragma unroll
            for (int i = 0; i < 4; i++)
                #pragma unroll
                for (int j = 0; j < 4; j++) {
                    asm volatile(
                        "mma.sync.aligned.m16n8k8.row.col.f32.tf32.tf32.f32 "
                        "{%0,%1,%2,%3}, {%4,%5,%6,%7}, {%8,%9}, {%0,%1,%2,%3};\n"
                        : "+f"(acc[i][j][0]), "+f"(acc[i][j][1]),
                          "+f"(acc[i][j][2]), "+f"(acc[i][j][3])
                        : "r"(a[i][0]), "r"(a[i][1]), "r"(a[i][2]), "r"(a[i][3]),
                          "r"(b[j][0]), "r"(b[j][1]));
                }
        }
        __syncthreads();
    }

    /* epilogue */
    #pragma unroll
    for (int i = 0; i < 4; i++) {
        int mA = m0 + wm*64 + i*16 + g;
        int mB = mA + 8;
        #pragma unroll
        for (int j = 0; j < 4; j++) {
            int n = n0 + wn*32 + j*8 + 2*c;
            float b0 = bias[n], b1 = bias[n+1];
            if (mA < M) {
                float v0 = acc[i][j][0] + b0;
                float v1 = acc[i][j][1] + b1;
                if (ACT == 1) {
                    v0 = v0 / (1.0f + expf(-1.702f * v0));
                    v1 = v1 / (1.0f + expf(-1.702f * v1));
                }
                *(float2*)(C + (size_t)mA*N + n) = make_float2(v0, v1);
            }
            if (mB < M) {
                float v0 = acc[i][j][2] + b0;
                float v1 = acc[i][j][3] + b1;
                if (ACT == 1) {
                    v0 = v0 / (1.0f + expf(-1.702f * v0));
                    v1 = v1 / (1.0f + expf(-1.702f * v1));
                }
                *(float2*)(C + (size_t)mB*N + n) = make_float2(v0, v1);
            }
        }
    }
}

/* ------------------------------------------------------------------ */
/* attn[b,h,s] = (q0[b,h,:]/8) . k[s,b,h,:]                           */
/* ------------------------------------------------------------------ */
__global__ void attn_kernel() {
    int bh = blockIdx.x;               // 0..127
    int b = bh >> 4, h = bh & 15;
    __shared__ float q[HD];
    int t = threadIdx.x;               // 128 threads
    if (t < HD) q[t] = g_q0[b*DIM + h*HD + t] * 0.125f;
    __syncthreads();
    for (int s = t; s < S_LEN; s += 128) {
        const float4* kr = (const float4*)(g_kv + (size_t)(s*BATCH + b)*2048 + h*HD);
        float acc = 0.0f;
        #pragma unroll
        for (int i = 0; i < 16; i++) {
            float4 kv4 = kr[i];
            acc += kv4.x*q[i*4+0] + kv4.y*q[i*4+1] + kv4.z*q[i*4+2] + kv4.w*q[i*4+3];
        }
        g_attn[bh*S_LEN + s] = acc;
    }
}

/* ------------------------------------------------------------------ */
/* Per (b,h): 17 softmax variants (16 masked boxes + 1 plain), then   */
/* P[17,577] @ V[577,64] with V staged through SMEM (read once).      */
/* ------------------------------------------------------------------ */
__global__ void softmax_av_kernel(const float* __restrict__ mask) {
    extern __shared__ float sm[];
    float* sm_p    = sm;               // 17*577 (padded region 9812)
    float* sm_attn = sm + 9812;        // 577 (padded 580)
    float* sm_v    = sm + 10392;       // 64*64, 16B aligned
    float* sm_red  = sm + 14488;       // 32
    int bh = blockIdx.x, b = bh >> 4, h = bh & 15;
    int t = threadIdx.x;               // 256

    for (int s = t; s < S_LEN; s += 256) sm_attn[s] = g_attn[bh*S_LEN + s];
    __syncthreads();

    for (int var = 0; var < 17; var++) {
        float* pr = sm_p + var * S_LEN;
        const float* mrow = (var < 16)
            ? (mask + (size_t)((b*NBOX + var)*NHEAD + h) * S_LEN) : (const float*)0;
        float mx = -3.0e38f;
        for (int s = t; s < S_LEN; s += 256) {
            float a = sm_attn[s] + (mrow ? mrow[s] : 0.0f);
            pr[s] = a;
            mx = fmaxf(mx, a);
        }
        mx = block_reduce(mx, sm_red, true);
        float sum = 0.0f;
        for (int s = t; s < S_LEN; s += 256) {
            float e = expf(pr[s] - mx);
            pr[s] = e;
            sum += e;
        }
        sum = block_reduce(sum, sm_red, false);
        float inv = 1.0f / sum;
        for (int s = t; s < S_LEN; s += 256) pr[s] *= inv;
        __syncthreads();
    }

    int e = t & 63, grp = t >> 6;      // grp uniform per warp
    float acc[5] = {0.f, 0.f, 0.f, 0.f, 0.f};
    for (int s0 = 0; s0 < S_LEN; s0 += 64) {
        __syncthreads();
        #pragma unroll
        for (int it = 0; it < 4; it++) {
            int idx = t + it * 256;           // 0..1023
            int r = idx >> 4, c4 = (idx & 15) << 2;
            int s = s0 + r;
            float4 vv = make_float4(0.f, 0.f, 0.f, 0.f);
            if (s < S_LEN)
                vv = *(const float4*)(g_kv + (size_t)(s*BATCH + b)*2048 + 1024 + h*HD + c4);
            *(float4*)(sm_v + r*64 + c4) = vv;
        }
        __syncthreads();
        int smax = min(64, S_LEN - s0);
        for (int r = 0; r < smax; r++) {
            float vv = sm_v[r*64 + e];
            #pragma unroll
            for (int i = 0; i < 4; i++)
                acc[i] += sm_p[(grp + 4*i)*S_LEN + s0 + r] * vv;
            if (grp == 0)
                acc[4] += sm_p[16*S_LEN + s0 + r] * vv;
        }
    }
    int col = h*HD + e;
    #pragma unroll
    for (int i = 0; i < 4; i++) {
        int var = grp + 4*i;
        g_attout[(size_t)(b*NBOX + var)*DIM + col] = acc[i];    // mask rows 0..127
    }
    if (grp == 0)
        g_attout[(size_t)(128 + b)*DIM + col] = acc[4];         // cls rows 128..135
}

/* ------------------------------------------------------------------ */
/* resid = x0 + proj; t = LN2(resid)                                  */
/* ------------------------------------------------------------------ */
__global__ void resid_ln2_kernel(const float* __restrict__ x,
                                 const float* __restrict__ g2,
                                 const float* __restrict__ b2) {
    __shared__ float sred[32];
    int m = blockIdx.x, t = threadIdx.x;
    int b = (m < 128) ? (m >> 4) : (m - 128);
    float4 xv = ((const float4*)(x      + (size_t)b*DIM))[t];   // x[0,b,:]
    float4 pv = ((const float4*)(g_proj + (size_t)m*DIM))[t];
    float4 r = make_float4(xv.x+pv.x, xv.y+pv.y, xv.z+pv.z, xv.w+pv.w);
    ((float4*)(g_resid + (size_t)m*DIM))[t] = r;
    float s = r.x + r.y + r.z + r.w;
    s = block_reduce(s, sred, false);
    float mean = s * (1.0f/DIM);
    float dx = r.x-mean, dy = r.y-mean, dz = r.z-mean, dw = r.w-mean;
    float ss = dx*dx + dy*dy + dz*dz + dw*dw;
    ss = block_reduce(ss, sred, false);
    float inv = rsqrtf(ss*(1.0f/DIM) + 1e-5f);
    float4 gv = ((const float4*)g2)[t];
    float4 bv = ((const float4*)b2)[t];
    float4 o;
    o.x = dx*inv*gv.x + bv.x;  o.y = dy*inv*gv.y + bv.y;
    o.z = dz*inv*gv.z + bv.z;  o.w = dw*inv*gv.w + bv.w;
    ((float4*)(g_t + (size_t)m*DIM))[t] = o;
}

/* ------------------------------------------------------------------ */
/* final = resid + mlp; scatter: rows 0..127 -> mask_cls, 128.. -> cls*/
/* ------------------------------------------------------------------ */
__global__ void final_kernel(float* __restrict__ out) {
    int m = blockIdx.x, t = threadIdx.x;
    float4 r  = ((const float4*)(g_resid + (size_t)m*DIM))[t];
    float4 mm = ((const float4*)(g_mlp   + (size_t)m*DIM))[t];
    float4 o = make_float4(r.x+mm.x, r.y+mm.y, r.z+mm.z, r.w+mm.w);
    float* dst = (m < 128) ? (out + (size_t)m*DIM)
                           : (out + 128*DIM + (size_t)(m-128)*DIM);
    ((float4*)dst)[t] = o;
}

/* ------------------------------------------------------------------ */
extern "C" void kernel_launch(void* const* d_in, const int* in_sizes, int n_in,
                              void* d_out, int out_size) {
    const float* x         = (const float*)d_in[0];
    const float* mask      = (const float*)d_in[1];
    /* d_in[2]=box_coords, d_in[3]=layers, d_in[4]=need_patch: unused */
    const float* in_proj_w = (const float*)d_in[5];
    const float* in_proj_b = (const float*)d_in[6];
    const float* out_w     = (const float*)d_in[7];
    const float* out_b     = (const float*)d_in[8];
    const float* ln1_g     = (const float*)d_in[9];
    const float* ln1_b     = (const float*)d_in[10];
    const float* ln2_g     = (const float*)d_in[11];
    const float* ln2_b     = (const float*)d_in[12];
    const float* fc_w      = (const float*)d_in[13];
    const float* fc_b      = (const float*)d_in[14];
    const float* proj_w    = (const float*)d_in[15];
    const float* proj_b    = (const float*)d_in[16];

    float *ph, *pkv, *pq0, *pattout, *pproj, *pt, *pfc, *pmlp;
    cudaGetSymbolAddress((void**)&ph,      g_h);
    cudaGetSymbolAddress((void**)&pkv,     g_kv);
    cudaGetSymbolAddress((void**)&pq0,     g_q0);
    cudaGetSymbolAddress((void**)&pattout, g_attout);
    cudaGetSymbolAddress((void**)&pproj,   g_proj);
    cudaGetSymbolAddress((void**)&pt,      g_t);
    cudaGetSymbolAddress((void**)&pfc,     g_fc);
    cudaGetSymbolAddress((void**)&pmlp,    g_mlp);

    /* 1. LN1 over all tokens */
    ln1_kernel<<<NROWS, 256>>>(x, ln1_g, ln1_b, ph);

    /* 2. K,V projection: [4616,1024] x [2048,1024]^T (dominant GEMM) */
    gemm_tc<0><<<dim3(2048/128, (NROWS+127)/128), 256>>>(
        ph, in_proj_w + 1024*1024, in_proj_b + 1024, pkv, NROWS, 2048, 1024);

    /* 3. Q projection, CLS row only (rows 0..7 of g_h are s=0) */
    gemm_tc<0><<<dim3(1024/128, 1), 256>>>(
        ph, in_proj_w, in_proj_b, pq0, BATCH, 1024, 1024);

    /* 4. attn logits */
    attn_kernel<<<BATCH*NHEAD, 128>>>();

    /* 5. 17-way softmax + P@V */
    cudaFuncSetAttribute(softmax_av_kernel,
                         cudaFuncAttributeMaxDynamicSharedMemorySize, 58080);
    softmax_av_kernel<<<BATCH*NHEAD, 256, 58080>>>(mask);

    /* 6. output projection (136 rows) */
    gemm_tc<0><<<dim3(1024/128, 2), 256>>>(
        pattout, out_w, out_b, pproj, MROW, 1024, 1024);

    /* 7. residual + LN2 */
    resid_ln2_kernel<<<MROW, 256>>>(x, ln2_g, ln2_b);

    /* 8. MLP fc + QuickGELU */
    gemm_tc<1><<<dim3(4096/128, 2), 256>>>(
        pt, fc_w, fc_b, pfc, MROW, 4096, 1024);

    /* 9. MLP proj */
    gemm_tc<0><<<dim3(1024/128, 2), 256>>>(
        pfc, proj_w, proj_b, pmlp, MROW, 1024, 4096);

    /* 10. residual + scatter to output */
    final_kernel<<<MROW, 256>>>((float*)d_out);
}

// round 3
// speedup vs baseline: 3.9106x; 1.7800x over previous
#include <cuda_runtime.h>
#include <math.h>
#include <stdint.h>

#define S_LEN 577
#define BATCH 8
#define DIM   1024
#define NHEAD 16
#define HD    64
#define NBOX  16
#define NROWS (S_LEN*BATCH)   /* 4616 */
#define MROW  136             /* 128 mask rows + 8 cls rows */

/* ------------------------------------------------------------------ */
/* scratch (device globals; no allocation allowed)                    */
/* ------------------------------------------------------------------ */
__device__ float g_h[NROWS*DIM];          // LN1 output (tf32-rounded)
__device__ float g_kv[NROWS*2048];        // [row, 0:1024]=k, [1024:2048]=v
__device__ float g_q0[BATCH*DIM];         // q for CLS token
__device__ float g_attn[BATCH*NHEAD*S_LEN];
__device__ float g_attout[MROW*DIM];      // attention output (tf32-rounded)
__device__ float g_proj[MROW*DIM];        // after out_w
__device__ float g_resid[MROW*DIM];
__device__ float g_t[MROW*DIM];           // LN2 output (tf32-rounded)
__device__ float g_fc[MROW*4096];         // fc+gelu output (tf32-rounded)
__device__ float g_mlp[MROW*DIM];
/* tf32-rounded weight copies */
__device__ float g_win[3*1024*1024];      // in_proj_w (q rows 0..1023, kv 1024..3071)
__device__ float g_wout[1024*1024];
__device__ float g_wfc[4*1024*1024];
__device__ float g_wproj[4*1024*1024];

/* ------------------------------------------------------------------ */
__device__ __forceinline__ float block_reduce(float v, float* sm, bool is_max) {
    int lane = threadIdx.x & 31, wid = threadIdx.x >> 5;
    #pragma unroll
    for (int o = 16; o; o >>= 1) {
        float u = __shfl_down_sync(0xffffffffu, v, o);
        v = is_max ? fmaxf(v, u) : v + u;
    }
    if (lane == 0) sm[wid] = v;
    __syncthreads();
    int nw = blockDim.x >> 5;
    if (wid == 0) {
        v = (lane < nw) ? sm[lane] : (is_max ? -3.0e38f : 0.0f);
        #pragma unroll
        for (int o = 16; o; o >>= 1) {
            float u = __shfl_down_sync(0xffffffffu, v, o);
            v = is_max ? fmaxf(v, u) : v + u;
        }
        if (lane == 0) sm[0] = v;
    }
    __syncthreads();
    float r = sm[0];
    __syncthreads();
    return r;
}

__device__ __forceinline__ float f2tf32f(float f) {
    uint32_t u;
    asm("cvt.rna.tf32.f32 %0, %1;" : "=r"(u) : "f"(f));
    return __uint_as_float(u);
}

__device__ __forceinline__ void cp_async16(uint32_t saddr, const void* gaddr, int src_size) {
    asm volatile("cp.async.cg.shared.global [%0], [%1], 16, %2;\n"
                 :: "r"(saddr), "l"(gaddr), "r"(src_size));
}

/* ------------------------------------------------------------------ */
/* elementwise tf32 rounding (weights)                                */
/* ------------------------------------------------------------------ */
__global__ void cvt_tf32_kernel(const float* __restrict__ in,
                                float* __restrict__ out, int n4) {
    int i = blockIdx.x * blockDim.x + threadIdx.x;
    if (i < n4) {
        float4 v = ((const float4*)in)[i];
        float4 o;
        o.x = f2tf32f(v.x); o.y = f2tf32f(v.y);
        o.z = f2tf32f(v.z); o.w = f2tf32f(v.w);
        ((float4*)out)[i] = o;
    }
}

/* ------------------------------------------------------------------ */
/* LayerNorm over 1024 cols, one block (256 thr) per row. out tf32.   */
/* ------------------------------------------------------------------ */
__global__ void ln1_kernel(const float* __restrict__ x,
                           const float* __restrict__ g,
                           const float* __restrict__ b,
                           float* __restrict__ out) {
    __shared__ float sred[32];
    int row = blockIdx.x, t = threadIdx.x;
    float4 v = ((const float4*)(x + (size_t)row*DIM))[t];
    float s = v.x + v.y + v.z + v.w;
    s = block_reduce(s, sred, false);
    float mean = s * (1.0f/DIM);
    float dx = v.x-mean, dy = v.y-mean, dz = v.z-mean, dw = v.w-mean;
    float ss = dx*dx + dy*dy + dz*dz + dw*dw;
    ss = block_reduce(ss, sred, false);
    float inv = rsqrtf(ss*(1.0f/DIM) + 1e-5f);
    float4 gv = ((const float4*)g)[t];
    float4 bv = ((const float4*)b)[t];
    float4 o;
    o.x = f2tf32f(dx*inv*gv.x + bv.x);  o.y = f2tf32f(dy*inv*gv.y + bv.y);
    o.z = f2tf32f(dz*inv*gv.z + bv.z);  o.w = f2tf32f(dw*inv*gv.w + bv.w);
    ((float4*)(out + (size_t)row*DIM))[t] = o;
}

/* ------------------------------------------------------------------ */
/* Tensor-core tf32 GEMM, cp.async double-buffered.                   */
/* C[m,n] = dot(A[m,:], W[n,:]) + bias[n]; inputs pre-rounded tf32.   */
/* BM=BN=128, BK=32, 256 thr = 8 warps (2x4 grid), warp tile 64x32,   */
/* mma.sync.m16n8k8.tf32. SMEM [m][36] (pad 4) conflict-free.         */
/* ACT: 1 = QuickGELU.  RND: 1 = round output to tf32.                */
/* ------------------------------------------------------------------ */
#define TSTRIDE 36
#define TILE_F (128*TSTRIDE)

template<int ACT, int RND>
__global__ void __launch_bounds__(256, 2)
gemm_tc(const float* __restrict__ A,
        const float* __restrict__ W,
        const float* __restrict__ bias,
        float* __restrict__ C,
        int M, int N, int K) {
    extern __shared__ float smem[];          // As[2][128][36] | Bs[2][128][36]
    float* Abuf = smem;
    float* Bbuf = smem + 2*TILE_F;
    uint32_t smem_u = (uint32_t)__cvta_generic_to_shared(smem);
    uint32_t Abase = smem_u;
    uint32_t Bbase = smem_u + 2*TILE_F*4;

    int tid = threadIdx.x;
    int warp = tid >> 5, lane = tid & 31;
    int wm = warp & 1, wn = warp >> 1;          // warp grid 2 (M) x 4 (N)
    int g = lane >> 2, c = lane & 3;
    int m0 = blockIdx.y * 128, n0 = blockIdx.x * 128;

    float acc[4][4][4];
    #pragma unroll
    for (int i = 0; i < 4; i++)
        #pragma unroll
        for (int j = 0; j < 4; j++)
            #pragma unroll
            for (int r = 0; r < 4; r++) acc[i][j][r] = 0.0f;

    const int NIT = K >> 5;

    /* tile loader: stage s, k-offset k0 */
    auto load_tile = [&](int s, int k0) {
        #pragma unroll
        for (int i = 0; i < 4; i++) {
            int ch = tid + i*256;            // 0..1023
            int m = ch >> 3, kq = ch & 7;
            const float* ga = A + (size_t)(m0 + m)*K + k0 + kq*4;
            int sz = (m0 + m < M) ? 16 : 0;
            cp_async16(Abase + (uint32_t)((s*TILE_F + m*TSTRIDE + kq*4)*4), ga, sz);
            const float* gb = W + (size_t)(n0 + m)*K + k0 + kq*4;
            cp_async16(Bbase + (uint32_t)((s*TILE_F + m*TSTRIDE + kq*4)*4), gb, 16);
        }
    };

    load_tile(0, 0);
    asm volatile("cp.async.commit_group;\n");

    int buf = 0;
    for (int it = 0; it < NIT; it++) {
        if (it + 1 < NIT) load_tile(buf ^ 1, (it + 1) << 5);
        asm volatile("cp.async.commit_group;\n");
        asm volatile("cp.async.wait_group 1;\n");
        __syncthreads();

        const float* As_s = Abuf + buf*TILE_F;
        const float* Bs_s = Bbuf + buf*TILE_F;
        #pragma unroll
        for (int kk = 0; kk < 32; kk += 8) {
            uint32_t a[4][4];
            #pragma unroll
            for (int i = 0; i < 4; i++) {
                int mr = (wm*64 + i*16 + g) * TSTRIDE;
                a[i][0] = __float_as_uint(As_s[mr            + kk + c    ]);
                a[i][1] = __float_as_uint(As_s[mr + 8*TSTRIDE + kk + c    ]);
                a[i][2] = __float_as_uint(As_s[mr            + kk + c + 4]);
                a[i][3] = __float_as_uint(As_s[mr + 8*TSTRIDE + kk + c + 4]);
            }
            uint32_t b[4][2];
            #pragma unroll
            for (int j = 0; j < 4; j++) {
                int nc = (wn*32 + j*8 + g) * TSTRIDE;
                b[j][0] = __float_as_uint(Bs_s[nc + kk + c    ]);
                b[j][1] = __float_as_uint(Bs_s[nc + kk + c + 4]);
            }
            #pragma unroll
            for (int i = 0; i < 4; i++)
                #pragma unroll
                for (int j = 0; j < 4; j++) {
                    asm volatile(
                        "mma.sync.aligned.m16n8k8.row.col.f32.tf32.tf32.f32 "
                        "{%0,%1,%2,%3}, {%4,%5,%6,%7}, {%8,%9}, {%0,%1,%2,%3};\n"
                        : "+f"(acc[i][j][0]), "+f"(acc[i][j][1]),
                          "+f"(acc[i][j][2]), "+f"(acc[i][j][3])
                        : "r"(a[i][0]), "r"(a[i][1]), "r"(a[i][2]), "r"(a[i][3]),
                          "r"(b[j][0]), "r"(b[j][1]));
                }
        }
        __syncthreads();
        buf ^= 1;
    }

    /* epilogue */
    #pragma unroll
    for (int i = 0; i < 4; i++) {
        int mA = m0 + wm*64 + i*16 + g;
        int mB = mA + 8;
        #pragma unroll
        for (int j = 0; j < 4; j++) {
            int n = n0 + wn*32 + j*8 + 2*c;
            float b0 = bias[n], b1 = bias[n+1];
            if (mA < M) {
                float v0 = acc[i][j][0] + b0;
                float v1 = acc[i][j][1] + b1;
                if (ACT == 1) {
                    v0 = v0 / (1.0f + expf(-1.702f * v0));
                    v1 = v1 / (1.0f + expf(-1.702f * v1));
                }
                if (RND == 1) { v0 = f2tf32f(v0); v1 = f2tf32f(v1); }
                *(float2*)(C + (size_t)mA*N + n) = make_float2(v0, v1);
            }
            if (mB < M) {
                float v0 = acc[i][j][2] + b0;
                float v1 = acc[i][j][3] + b1;
                if (ACT == 1) {
                    v0 = v0 / (1.0f + expf(-1.702f * v0));
                    v1 = v1 / (1.0f + expf(-1.702f * v1));
                }
                if (RND == 1) { v0 = f2tf32f(v0); v1 = f2tf32f(v1); }
                *(float2*)(C + (size_t)mB*N + n) = make_float2(v0, v1);
            }
        }
    }
}

/* ------------------------------------------------------------------ */
/* attn[b,h,s] = (q0[b,h,:]/8) . k[s,b,h,:]                           */
/* ------------------------------------------------------------------ */
__global__ void attn_kernel() {
    int bh = blockIdx.x;               // 0..127
    int b = bh >> 4, h = bh & 15;
    __shared__ float q[HD];
    int t = threadIdx.x;               // 128 threads
    if (t < HD) q[t] = g_q0[b*DIM + h*HD + t] * 0.125f;
    __syncthreads();
    for (int s = t; s < S_LEN; s += 128) {
        const float4* kr = (const float4*)(g_kv + (size_t)(s*BATCH + b)*2048 + h*HD);
        float acc = 0.0f;
        #pragma unroll
        for (int i = 0; i < 16; i++) {
            float4 kv4 = kr[i];
            acc += kv4.x*q[i*4+0] + kv4.y*q[i*4+1] + kv4.z*q[i*4+2] + kv4.w*q[i*4+3];
        }
        g_attn[bh*S_LEN + s] = acc;
    }
}

/* ------------------------------------------------------------------ */
/* Per (b,h): 17 softmax variants (16 masked boxes + 1 plain), then   */
/* P[17,577] @ V[577,64] with V staged through SMEM.                  */
/* ------------------------------------------------------------------ */
__global__ void softmax_av_kernel(const float* __restrict__ mask) {
    extern __shared__ float sm[];
    float* sm_p    = sm;               // 17*577 (padded region 9812)
    float* sm_attn = sm + 9812;        // 577 (padded 580)
    float* sm_v    = sm + 10392;       // 64*64
    float* sm_red  = sm + 14488;       // 32
    int bh = blockIdx.x, b = bh >> 4, h = bh & 15;
    int t = threadIdx.x;               // 256

    for (int s = t; s < S_LEN; s += 256) sm_attn[s] = g_attn[bh*S_LEN + s];
    __syncthreads();

    for (int var = 0; var < 17; var++) {
        float* pr = sm_p + var * S_LEN;
        const float* mrow = (var < 16)
            ? (mask + (size_t)((b*NBOX + var)*NHEAD + h) * S_LEN) : (const float*)0;
        float mx = -3.0e38f;
        for (int s = t; s < S_LEN; s += 256) {
            float a = sm_attn[s] + (mrow ? mrow[s] : 0.0f);
            pr[s] = a;
            mx = fmaxf(mx, a);
        }
        mx = block_reduce(mx, sm_red, true);
        float sum = 0.0f;
        for (int s = t; s < S_LEN; s += 256) {
            float e = expf(pr[s] - mx);
            pr[s] = e;
            sum += e;
        }
        sum = block_reduce(sum, sm_red, false);
        float inv = 1.0f / sum;
        for (int s = t; s < S_LEN; s += 256) pr[s] *= inv;
        __syncthreads();
    }

    int e = t & 63, grp = t >> 6;
    float acc[5] = {0.f, 0.f, 0.f, 0.f, 0.f};
    for (int s0 = 0; s0 < S_LEN; s0 += 64) {
        __syncthreads();
        #pragma unroll
        for (int it = 0; it < 4; it++) {
            int idx = t + it * 256;
            int r = idx >> 4, c4 = (idx & 15) << 2;
            int s = s0 + r;
            float4 vv = make_float4(0.f, 0.f, 0.f, 0.f);
            if (s < S_LEN)
                vv = *(const float4*)(g_kv + (size_t)(s*BATCH + b)*2048 + 1024 + h*HD + c4);
            *(float4*)(sm_v + r*64 + c4) = vv;
        }
        __syncthreads();
        int smax = min(64, S_LEN - s0);
        for (int r = 0; r < smax; r++) {
            float vv = sm_v[r*64 + e];
            #pragma unroll
            for (int i = 0; i < 4; i++)
                acc[i] += sm_p[(grp + 4*i)*S_LEN + s0 + r] * vv;
            if (grp == 0)
                acc[4] += sm_p[16*S_LEN + s0 + r] * vv;
        }
    }
    int col = h*HD + e;
    #pragma unroll
    for (int i = 0; i < 4; i++) {
        int var = grp + 4*i;
        g_attout[(size_t)(b*NBOX + var)*DIM + col] = f2tf32f(acc[i]);
    }
    if (grp == 0)
        g_attout[(size_t)(128 + b)*DIM + col] = f2tf32f(acc[4]);
}

/* ------------------------------------------------------------------ */
/* resid = x0 + proj; t = LN2(resid) rounded to tf32                  */
/* ------------------------------------------------------------------ */
__global__ void resid_ln2_kernel(const float* __restrict__ x,
                                 const float* __restrict__ g2,
                                 const float* __restrict__ b2) {
    __shared__ float sred[32];
    int m = blockIdx.x, t = threadIdx.x;
    int b = (m < 128) ? (m >> 4) : (m - 128);
    float4 xv = ((const float4*)(x      + (size_t)b*DIM))[t];
    float4 pv = ((const float4*)(g_proj + (size_t)m*DIM))[t];
    float4 r = make_float4(xv.x+pv.x, xv.y+pv.y, xv.z+pv.z, xv.w+pv.w);
    ((float4*)(g_resid + (size_t)m*DIM))[t] = r;
    float s = r.x + r.y + r.z + r.w;
    s = block_reduce(s, sred, false);
    float mean = s * (1.0f/DIM);
    float dx = r.x-mean, dy = r.y-mean, dz = r.z-mean, dw = r.w-mean;
    float ss = dx*dx + dy*dy + dz*dz + dw*dw;
    ss = block_reduce(ss, sred, false);
    float inv = rsqrtf(ss*(1.0f/DIM) + 1e-5f);
    float4 gv = ((const float4*)g2)[t];
    float4 bv = ((const float4*)b2)[t];
    float4 o;
    o.x = f2tf32f(dx*inv*gv.x + bv.x);  o.y = f2tf32f(dy*inv*gv.y + bv.y);
    o.z = f2tf32f(dz*inv*gv.z + bv.z);  o.w = f2tf32f(dw*inv*gv.w + bv.w);
    ((float4*)(g_t + (size_t)m*DIM))[t] = o;
}

/* ------------------------------------------------------------------ */
__global__ void final_kernel(float* __restrict__ out) {
    int m = blockIdx.x, t = threadIdx.x;
    float4 r  = ((const float4*)(g_resid + (size_t)m*DIM))[t];
    float4 mm = ((const float4*)(g_mlp   + (size_t)m*DIM))[t];
    float4 o = make_float4(r.x+mm.x, r.y+mm.y, r.z+mm.z, r.w+mm.w);
    float* dst = (m < 128) ? (out + (size_t)m*DIM)
                           : (out + 128*DIM + (size_t)(m-128)*DIM);
    ((float4*)dst)[t] = o;
}

/* ------------------------------------------------------------------ */
extern "C" void kernel_launch(void* const* d_in, const int* in_sizes, int n_in,
                              void* d_out, int out_size) {
    const float* x         = (const float*)d_in[0];
    const float* mask      = (const float*)d_in[1];
    const float* in_proj_w = (const float*)d_in[5];
    const float* in_proj_b = (const float*)d_in[6];
    const float* out_w     = (const float*)d_in[7];
    const float* out_b     = (const float*)d_in[8];
    const float* ln1_g     = (const float*)d_in[9];
    const float* ln1_b     = (const float*)d_in[10];
    const float* ln2_g     = (const float*)d_in[11];
    const float* ln2_b     = (const float*)d_in[12];
    const float* fc_w      = (const float*)d_in[13];
    const float* fc_b      = (const float*)d_in[14];
    const float* proj_w    = (const float*)d_in[15];
    const float* proj_b    = (const float*)d_in[16];

    float *ph, *pkv, *pq0, *pattout, *pproj, *pt, *pfc, *pmlp;
    float *pwin, *pwout, *pwfc, *pwproj;
    cudaGetSymbolAddress((void**)&ph,      g_h);
    cudaGetSymbolAddress((void**)&pkv,     g_kv);
    cudaGetSymbolAddress((void**)&pq0,     g_q0);
    cudaGetSymbolAddress((void**)&pattout, g_attout);
    cudaGetSymbolAddress((void**)&pproj,   g_proj);
    cudaGetSymbolAddress((void**)&pt,      g_t);
    cudaGetSymbolAddress((void**)&pfc,     g_fc);
    cudaGetSymbolAddress((void**)&pmlp,    g_mlp);
    cudaGetSymbolAddress((void**)&pwin,    g_win);
    cudaGetSymbolAddress((void**)&pwout,   g_wout);
    cudaGetSymbolAddress((void**)&pwfc,    g_wfc);
    cudaGetSymbolAddress((void**)&pwproj,  g_wproj);

    const int GEMM_SMEM = 2*2*TILE_F*4;   /* 73728 B */
    cudaFuncSetAttribute(gemm_tc<0,0>, cudaFuncAttributeMaxDynamicSharedMemorySize, GEMM_SMEM);
    cudaFuncSetAttribute(gemm_tc<1,1>, cudaFuncAttributeMaxDynamicSharedMemorySize, GEMM_SMEM);
    cudaFuncSetAttribute(softmax_av_kernel, cudaFuncAttributeMaxDynamicSharedMemorySize, 58080);

    /* 1-4. weight tf32 rounding */
    cvt_tf32_kernel<<<(3*1024*1024/4 + 255)/256, 256>>>(in_proj_w, pwin, 3*1024*1024/4);
    cvt_tf32_kernel<<<(1024*1024/4 + 255)/256, 256>>>(out_w, pwout, 1024*1024/4);
    cvt_tf32_kernel<<<(4*1024*1024/4 + 255)/256, 256>>>(fc_w, pwfc, 4*1024*1024/4);
    cvt_tf32_kernel<<<(4*1024*1024/4 + 255)/256, 256>>>(proj_w, pwproj, 4*1024*1024/4);

    /* 5. LN1 over all tokens (tf32-rounded out) */
    ln1_kernel<<<NROWS, 256>>>(x, ln1_g, ln1_b, ph);

    /* 6. K,V projection: [4616,1024] x [2048,1024]^T  (launch #6 for ncu) */
    gemm_tc<0,0><<<dim3(2048/128, (NROWS+127)/128), 256, GEMM_SMEM>>>(
        ph, pwin + 1024*1024, in_proj_b + 1024, pkv, NROWS, 2048, 1024);

    /* 7. Q projection, CLS rows only */
    gemm_tc<0,0><<<dim3(1024/128, 1), 256, GEMM_SMEM>>>(
        ph, pwin, in_proj_b, pq0, BATCH, 1024, 1024);

    /* 8. attn logits */
    attn_kernel<<<BATCH*NHEAD, 128>>>();

    /* 9. 17-way softmax + P@V */
    softmax_av_kernel<<<BATCH*NHEAD, 256, 58080>>>(mask);

    /* 10. output projection (136 rows) */
    gemm_tc<0,0><<<dim3(1024/128, 2), 256, GEMM_SMEM>>>(
        pattout, pwout, out_b, pproj, MROW, 1024, 1024);

    /* 11. residual + LN2 */
    resid_ln2_kernel<<<MROW, 256>>>(x, ln2_g, ln2_b);

    /* 12. MLP fc + QuickGELU (output tf32-rounded) */
    gemm_tc<1,1><<<dim3(4096/128, 2), 256, GEMM_SMEM>>>(
        pt, pwfc, fc_b, pfc, MROW, 4096, 1024);

    /* 13. MLP proj */
    gemm_tc<0,0><<<dim3(1024/128, 2), 256, GEMM_SMEM>>>(
        pfc, pwproj, proj_b, pmlp, MROW, 1024, 4096);

    /* 14. residual + scatter to output */
    final_kernel<<<MROW, 256>>>((float*)d_out);
}

// round 5
// speedup vs baseline: 4.2084x; 1.0761x over previous
#include <cuda_runtime.h>
#include <math.h>
#include <stdint.h>

#define S_LEN 577
#define BATCH 8
#define DIM   1024
#define NHEAD 16
#define HD    64
#define NBOX  16
#define NROWS (S_LEN*BATCH)   /* 4616 */
#define MROW  136             /* 128 mask rows + 8 cls rows */

/* ------------------------------------------------------------------ */
/* scratch (device globals; no allocation allowed)                    */
/* ------------------------------------------------------------------ */
__device__ float g_h[NROWS*DIM];          // LN1 output (tf32-rounded)
__device__ float g_kv[NROWS*2048];        // [row, 0:1024]=k, [1024:2048]=v
__device__ float g_q0[BATCH*DIM];
__device__ float g_attn[BATCH*NHEAD*S_LEN];
__device__ float g_attout[MROW*DIM];      // tf32-rounded
__device__ float g_proj[MROW*DIM];
__device__ float g_resid[MROW*DIM];
__device__ float g_t[MROW*DIM];           // tf32-rounded
__device__ float g_fc[MROW*4096];         // tf32-rounded
__device__ float g_mlp[MROW*DIM];
/* tf32-rounded weight copies */
__device__ float g_wkv[2048*1024];
__device__ float g_wout[1024*1024];
__device__ float g_wfc[4*1024*1024];
__device__ float g_wproj[4*1024*1024];

/* ------------------------------------------------------------------ */
__device__ __forceinline__ float block_reduce(float v, float* sm, bool is_max) {
    int lane = threadIdx.x & 31, wid = threadIdx.x >> 5;
    #pragma unroll
    for (int o = 16; o; o >>= 1) {
        float u = __shfl_down_sync(0xffffffffu, v, o);
        v = is_max ? fmaxf(v, u) : v + u;
    }
    if (lane == 0) sm[wid] = v;
    __syncthreads();
    int nw = blockDim.x >> 5;
    if (wid == 0) {
        v = (lane < nw) ? sm[lane] : (is_max ? -3.0e38f : 0.0f);
        #pragma unroll
        for (int o = 16; o; o >>= 1) {
            float u = __shfl_down_sync(0xffffffffu, v, o);
            v = is_max ? fmaxf(v, u) : v + u;
        }
        if (lane == 0) sm[0] = v;
    }
    __syncthreads();
    float r = sm[0];
    __syncthreads();
    return r;
}

__device__ __forceinline__ float f2tf32f(float f) {
    uint32_t u;
    asm("cvt.rna.tf32.f32 %0, %1;" : "=r"(u) : "f"(f));
    return __uint_as_float(u);
}

__device__ __forceinline__ void cp_async16(uint32_t saddr, const void* gaddr, int src_size) {
    asm volatile("cp.async.cg.shared.global [%0], [%1], 16, %2;\n"
                 :: "r"(saddr), "l"(gaddr), "r"(src_size));
}

__device__ __forceinline__ uint32_t smem_u32(const void* p) {
    return (uint32_t)__cvta_generic_to_shared(p);
}

/* ------------------------------------------------------------------ */
__global__ void cvt_tf32_kernel(const float* __restrict__ in,
                                float* __restrict__ out, int n4) {
    int i = blockIdx.x * blockDim.x + threadIdx.x;
    if (i < n4) {
        float4 v = ((const float4*)in)[i];
        float4 o;
        o.x = f2tf32f(v.x); o.y = f2tf32f(v.y);
        o.z = f2tf32f(v.z); o.w = f2tf32f(v.w);
        ((float4*)out)[i] = o;
    }
}

/* ------------------------------------------------------------------ */
/* LayerNorm over 1024 cols, one block (256 thr) per row. out tf32.   */
/* ------------------------------------------------------------------ */
__global__ void ln1_kernel(const float* __restrict__ x,
                           const float* __restrict__ g,
                           const float* __restrict__ b,
                           float* __restrict__ out) {
    __shared__ float sred[32];
    int row = blockIdx.x, t = threadIdx.x;
    float4 v = ((const float4*)(x + (size_t)row*DIM))[t];
    float s = v.x + v.y + v.z + v.w;
    s = block_reduce(s, sred, false);
    float mean = s * (1.0f/DIM);
    float dx = v.x-mean, dy = v.y-mean, dz = v.z-mean, dw = v.w-mean;
    float ss = dx*dx + dy*dy + dz*dz + dw*dw;
    ss = block_reduce(ss, sred, false);
    float inv = rsqrtf(ss*(1.0f/DIM) + 1e-5f);
    float4 gv = ((const float4*)g)[t];
    float4 bv = ((const float4*)b)[t];
    float4 o;
    o.x = f2tf32f(dx*inv*gv.x + bv.x);  o.y = f2tf32f(dy*inv*gv.y + bv.y);
    o.z = f2tf32f(dz*inv*gv.z + bv.z);  o.w = f2tf32f(dw*inv*gv.w + bv.w);
    ((float4*)(out + (size_t)row*DIM))[t] = o;
}

/* ------------------------------------------------------------------ */
/* BIG tf32 GEMM for the KV projection.                               */
/* BM=128, BN=256, BK=32, 256 thr = 8 warps (2 M x 4 N),              */
/* warp tile 64x64 (4x8 m16n8k8 frags). cp.async double-buffered.     */
/* ------------------------------------------------------------------ */
#define BSTRIDE 36
#define A_TILE_F (128*BSTRIDE)
#define B_TILE_F (256*BSTRIDE)
#define BIG_SMEM ((2*A_TILE_F + 2*B_TILE_F)*4)   /* 110592 B */

__global__ void __launch_bounds__(256, 1)
gemm_big(const float* __restrict__ A,
         const float* __restrict__ W,
         const float* __restrict__ bias,
         float* __restrict__ C,
         int M, int N, int K) {
    extern __shared__ float smemf[];
    float* Abuf = smemf;                       // [2][128][36]
    float* Bbuf = smemf + 2*A_TILE_F;          // [2][256][36]
    uint32_t Abase = smem_u32(Abuf);
    uint32_t Bbase = smem_u32(Bbuf);

    int tid = threadIdx.x;
    int warp = tid >> 5, lane = tid & 31;
    int wm = warp & 1, wn = warp >> 1;          // 2 x 4 warps
    int g = lane >> 2, c = lane & 3;
    int m0 = blockIdx.y * 128, n0 = blockIdx.x * 256;

    float acc[4][8][4];
    #pragma unroll
    for (int i = 0; i < 4; i++)
        #pragma unroll
        for (int j = 0; j < 8; j++)
            #pragma unroll
            for (int r = 0; r < 4; r++) acc[i][j][r] = 0.0f;

    const int NIT = K >> 5;

    auto load_tile = [&](int s, int k0) {
        /* A: 128 rows x 8 kq -> 1024 chunks, 4 per thread */
        #pragma unroll
        for (int i = 0; i < 4; i++) {
            int ch = tid + i*256;
            int m = ch >> 3, kq = ch & 7;
            const float* ga = A + (size_t)(m0 + m)*K + k0 + kq*4;
            int sz = (m0 + m < M) ? 16 : 0;
            cp_async16(Abase + (uint32_t)((s*A_TILE_F + m*BSTRIDE + kq*4)*4), ga, sz);
        }
        /* B: 256 rows x 8 kq -> 2048 chunks, 8 per thread */
        #pragma unroll
        for (int i = 0; i < 8; i++) {
            int ch = tid + i*256;
            int n = ch >> 3, kq = ch & 7;
            const float* gb = W + (size_t)(n0 + n)*K + k0 + kq*4;
            cp_async16(Bbase + (uint32_t)((s*B_TILE_F + n*BSTRIDE + kq*4)*4), gb, 16);
        }
    };

    load_tile(0, 0);
    asm volatile("cp.async.commit_group;\n");

    int buf = 0;
    for (int it = 0; it < NIT; it++) {
        if (it + 1 < NIT) load_tile(buf ^ 1, (it + 1) << 5);
        asm volatile("cp.async.commit_group;\n");
        asm volatile("cp.async.wait_group 1;\n");
        __syncthreads();

        const float* As_s = Abuf + buf*A_TILE_F;
        const float* Bs_s = Bbuf + buf*B_TILE_F;
        #pragma unroll
        for (int kk = 0; kk < 32; kk += 8) {
            uint32_t a[4][4];
            #pragma unroll
            for (int i = 0; i < 4; i++) {
                int mr = (wm*64 + i*16 + g) * BSTRIDE;
                a[i][0] = __float_as_uint(As_s[mr              + kk + c    ]);
                a[i][1] = __float_as_uint(As_s[mr + 8*BSTRIDE  + kk + c    ]);
                a[i][2] = __float_as_uint(As_s[mr              + kk + c + 4]);
                a[i][3] = __float_as_uint(As_s[mr + 8*BSTRIDE  + kk + c + 4]);
            }
            uint32_t b[8][2];
            #pragma unroll
            for (int j = 0; j < 8; j++) {
                int nc = (wn*64 + j*8 + g) * BSTRIDE;
                b[j][0] = __float_as_uint(Bs_s[nc + kk + c    ]);
                b[j][1] = __float_as_uint(Bs_s[nc + kk + c + 4]);
            }
            #pragma unroll
            for (int i = 0; i < 4; i++)
                #pragma unroll
                for (int j = 0; j < 8; j++) {
                    asm volatile(
                        "mma.sync.aligned.m16n8k8.row.col.f32.tf32.tf32.f32 "
                        "{%0,%1,%2,%3}, {%4,%5,%6,%7}, {%8,%9}, {%0,%1,%2,%3};\n"
                        : "+f"(acc[i][j][0]), "+f"(acc[i][j][1]),
                          "+f"(acc[i][j][2]), "+f"(acc[i][j][3])
                        : "r"(a[i][0]), "r"(a[i][1]), "r"(a[i][2]), "r"(a[i][3]),
                          "r"(b[j][0]), "r"(b[j][1]));
                }
        }
        __syncthreads();
        buf ^= 1;
    }

    #pragma unroll
    for (int i = 0; i < 4; i++) {
        int mA = m0 + wm*64 + i*16 + g;
        int mB = mA + 8;
        #pragma unroll
        for (int j = 0; j < 8; j++) {
            int n = n0 + wn*64 + j*8 + 2*c;
            float b0 = bias[n], b1 = bias[n+1];
            if (mA < M)
                *(float2*)(C + (size_t)mA*N + n) =
                    make_float2(acc[i][j][0] + b0, acc[i][j][1] + b1);
            if (mB < M)
                *(float2*)(C + (size_t)mB*N + n) =
                    make_float2(acc[i][j][2] + b0, acc[i][j][3] + b1);
        }
    }
}

/* ------------------------------------------------------------------ */
/* mma.sync tf32 GEMM for the small GEMMs (round-3 proven)            */
/* ------------------------------------------------------------------ */
#define TSTRIDE 36
#define TILE_F (128*TSTRIDE)

template<int ACT, int RND>
__global__ void __launch_bounds__(256, 2)
gemm_tc(const float* __restrict__ A,
        const float* __restrict__ W,
        const float* __restrict__ bias,
        float* __restrict__ C,
        int M, int N, int K) {
    extern __shared__ float smemf[];
    float* Abuf = smemf;
    float* Bbuf = smemf + 2*TILE_F;
    uint32_t Abase = smem_u32(Abuf);
    uint32_t Bbase = smem_u32(Bbuf);

    int tid = threadIdx.x;
    int warp = tid >> 5, lane = tid & 31;
    int wm = warp & 1, wn = warp >> 1;
    int g = lane >> 2, c = lane & 3;
    int m0 = blockIdx.y * 128, n0 = blockIdx.x * 128;

    float acc[4][4][4];
    #pragma unroll
    for (int i = 0; i < 4; i++)
        #pragma unroll
        for (int j = 0; j < 4; j++)
            #pragma unroll
            for (int r = 0; r < 4; r++) acc[i][j][r] = 0.0f;

    const int NIT = K >> 5;

    auto load_tile = [&](int s, int k0) {
        #pragma unroll
        for (int i = 0; i < 4; i++) {
            int ch = tid + i*256;
            int m = ch >> 3, kq = ch & 7;
            const float* ga = A + (size_t)(m0 + m)*K + k0 + kq*4;
            int sz = (m0 + m < M) ? 16 : 0;
            cp_async16(Abase + (uint32_t)((s*TILE_F + m*TSTRIDE + kq*4)*4), ga, sz);
            const float* gb = W + (size_t)(n0 + m)*K + k0 + kq*4;
            cp_async16(Bbase + (uint32_t)((s*TILE_F + m*TSTRIDE + kq*4)*4), gb, 16);
        }
    };

    load_tile(0, 0);
    asm volatile("cp.async.commit_group;\n");

    int buf = 0;
    for (int it = 0; it < NIT; it++) {
        if (it + 1 < NIT) load_tile(buf ^ 1, (it + 1) << 5);
        asm volatile("cp.async.commit_group;\n");
        asm volatile("cp.async.wait_group 1;\n");
        __syncthreads();

        const float* As_s = Abuf + buf*TILE_F;
        const float* Bs_s = Bbuf + buf*TILE_F;
        #pragma unroll
        for (int kk = 0; kk < 32; kk += 8) {
            uint32_t a[4][4];
            #pragma unroll
            for (int i = 0; i < 4; i++) {
                int mr = (wm*64 + i*16 + g) * TSTRIDE;
                a[i][0] = __float_as_uint(As_s[mr            + kk + c    ]);
                a[i][1] = __float_as_uint(As_s[mr + 8*TSTRIDE + kk + c    ]);
                a[i][2] = __float_as_uint(As_s[mr            + kk + c + 4]);
                a[i][3] = __float_as_uint(As_s[mr + 8*TSTRIDE + kk + c + 4]);
            }
            uint32_t b[4][2];
            #pragma unroll
            for (int j = 0; j < 4; j++) {
                int nc = (wn*32 + j*8 + g) * TSTRIDE;
                b[j][0] = __float_as_uint(Bs_s[nc + kk + c    ]);
                b[j][1] = __float_as_uint(Bs_s[nc + kk + c + 4]);
            }
            #pragma unroll
            for (int i = 0; i < 4; i++)
                #pragma unroll
                for (int j = 0; j < 4; j++) {
                    asm volatile(
                        "mma.sync.aligned.m16n8k8.row.col.f32.tf32.tf32.f32 "
                        "{%0,%1,%2,%3}, {%4,%5,%6,%7}, {%8,%9}, {%0,%1,%2,%3};\n"
                        : "+f"(acc[i][j][0]), "+f"(acc[i][j][1]),
                          "+f"(acc[i][j][2]), "+f"(acc[i][j][3])
                        : "r"(a[i][0]), "r"(a[i][1]), "r"(a[i][2]), "r"(a[i][3]),
                          "r"(b[j][0]), "r"(b[j][1]));
                }
        }
        __syncthreads();
        buf ^= 1;
    }

    #pragma unroll
    for (int i = 0; i < 4; i++) {
        int mA = m0 + wm*64 + i*16 + g;
        int mB = mA + 8;
        #pragma unroll
        for (int j = 0; j < 4; j++) {
            int n = n0 + wn*32 + j*8 + 2*c;
            float b0 = bias[n], b1 = bias[n+1];
            if (mA < M) {
                float v0 = acc[i][j][0] + b0;
                float v1 = acc[i][j][1] + b1;
                if (ACT == 1) {
                    v0 = v0 / (1.0f + expf(-1.702f * v0));
                    v1 = v1 / (1.0f + expf(-1.702f * v1));
                }
                if (RND == 1) { v0 = f2tf32f(v0); v1 = f2tf32f(v1); }
                *(float2*)(C + (size_t)mA*N + n) = make_float2(v0, v1);
            }
            if (mB < M) {
                float v0 = acc[i][j][2] + b0;
                float v1 = acc[i][j][3] + b1;
                if (ACT == 1) {
                    v0 = v0 / (1.0f + expf(-1.702f * v0));
                    v1 = v1 / (1.0f + expf(-1.702f * v1));
                }
                if (RND == 1) { v0 = f2tf32f(v0); v1 = f2tf32f(v1); }
                *(float2*)(C + (size_t)mB*N + n) = make_float2(v0, v1);
            }
        }
    }
}

/* ------------------------------------------------------------------ */
/* Q projection, CLS rows only: warp-per-output fp32                  */
/* ------------------------------------------------------------------ */
__global__ void q_kernel(const float* __restrict__ w, const float* __restrict__ b) {
    int gw = (blockIdx.x * blockDim.x + threadIdx.x) >> 5;
    int lane = threadIdx.x & 31;
    int m = gw >> 10, n = gw & 1023;
    const float4* hr = (const float4*)(g_h + (size_t)m*DIM);
    const float4* wr = (const float4*)(w + (size_t)n*DIM);
    float acc = 0.0f;
    #pragma unroll
    for (int i = 0; i < 8; i++) {
        float4 a = hr[lane + i*32], ww = wr[lane + i*32];
        acc += a.x*ww.x + a.y*ww.y + a.z*ww.z + a.w*ww.w;
    }
    #pragma unroll
    for (int o = 16; o; o >>= 1) acc += __shfl_down_sync(0xffffffffu, acc, o);
    if (lane == 0) g_q0[m*DIM + n] = acc + b[n];
}

/* ------------------------------------------------------------------ */
__global__ void attn_kernel() {
    int bh = blockIdx.x;
    int b = bh >> 4, h = bh & 15;
    __shared__ float q[HD];
    int t = threadIdx.x;
    if (t < HD) q[t] = g_q0[b*DIM + h*HD + t] * 0.125f;
    __syncthreads();
    for (int s = t; s < S_LEN; s += 128) {
        const float4* kr = (const float4*)(g_kv + (size_t)(s*BATCH + b)*2048 + h*HD);
        float acc = 0.0f;
        #pragma unroll
        for (int i = 0; i < 16; i++) {
            float4 kv4 = kr[i];
            acc += kv4.x*q[i*4+0] + kv4.y*q[i*4+1] + kv4.z*q[i*4+2] + kv4.w*q[i*4+3];
        }
        g_attn[bh*S_LEN + s] = acc;
    }
}

/* ------------------------------------------------------------------ */
__global__ void softmax_av_kernel(const float* __restrict__ mask) {
    extern __shared__ float sm[];
    float* sm_p    = sm;
    float* sm_attn = sm + 9812;
    float* sm_v    = sm + 10392;
    float* sm_red  = sm + 14488;
    int bh = blockIdx.x, b = bh >> 4, h = bh & 15;
    int t = threadIdx.x;

    for (int s = t; s < S_LEN; s += 256) sm_attn[s] = g_attn[bh*S_LEN + s];
    __syncthreads();

    for (int var = 0; var < 17; var++) {
        float* pr = sm_p + var * S_LEN;
        const float* mrow = (var < 16)
            ? (mask + (size_t)((b*NBOX + var)*NHEAD + h) * S_LEN) : (const float*)0;
        float mx = -3.0e38f;
        for (int s = t; s < S_LEN; s += 256) {
            float a = sm_attn[s] + (mrow ? mrow[s] : 0.0f);
            pr[s] = a;
            mx = fmaxf(mx, a);
        }
        mx = block_reduce(mx, sm_red, true);
        float sum = 0.0f;
        for (int s = t; s < S_LEN; s += 256) {
            float e = expf(pr[s] - mx);
            pr[s] = e;
            sum += e;
        }
        sum = block_reduce(sum, sm_red, false);
        float inv = 1.0f / sum;
        for (int s = t; s < S_LEN; s += 256) pr[s] *= inv;
        __syncthreads();
    }

    int e = t & 63, grp = t >> 6;
    float acc[5] = {0.f, 0.f, 0.f, 0.f, 0.f};
    for (int s0 = 0; s0 < S_LEN; s0 += 64) {
        __syncthreads();
        #pragma unroll
        for (int it = 0; it < 4; it++) {
            int idx = t + it * 256;
            int r = idx >> 4, c4 = (idx & 15) << 2;
            int s = s0 + r;
            float4 vv = make_float4(0.f, 0.f, 0.f, 0.f);
            if (s < S_LEN)
                vv = *(const float4*)(g_kv + (size_t)(s*BATCH + b)*2048 + 1024 + h*HD + c4);
            *(float4*)(sm_v + r*64 + c4) = vv;
        }
        __syncthreads();
        int smax = min(64, S_LEN - s0);
        for (int r = 0; r < smax; r++) {
            float vv = sm_v[r*64 + e];
            #pragma unroll
            for (int i = 0; i < 4; i++)
                acc[i] += sm_p[(grp + 4*i)*S_LEN + s0 + r] * vv;
            if (grp == 0)
                acc[4] += sm_p[16*S_LEN + s0 + r] * vv;
        }
    }
    int col = h*HD + e;
    #pragma unroll
    for (int i = 0; i < 4; i++) {
        int var = grp + 4*i;
        g_attout[(size_t)(b*NBOX + var)*DIM + col] = f2tf32f(acc[i]);
    }
    if (grp == 0)
        g_attout[(size_t)(128 + b)*DIM + col] = f2tf32f(acc[4]);
}

/* ------------------------------------------------------------------ */
__global__ void resid_ln2_kernel(const float* __restrict__ x,
                                 const float* __restrict__ g2,
                                 const float* __restrict__ b2) {
    __shared__ float sred[32];
    int m = blockIdx.x, t = threadIdx.x;
    int b = (m < 128) ? (m >> 4) : (m - 128);
    float4 xv = ((const float4*)(x      + (size_t)b*DIM))[t];
    float4 pv = ((const float4*)(g_proj + (size_t)m*DIM))[t];
    float4 r = make_float4(xv.x+pv.x, xv.y+pv.y, xv.z+pv.z, xv.w+pv.w);
    ((float4*)(g_resid + (size_t)m*DIM))[t] = r;
    float s = r.x + r.y + r.z + r.w;
    s = block_reduce(s, sred, false);
    float mean = s * (1.0f/DIM);
    float dx = r.x-mean, dy = r.y-mean, dz = r.z-mean, dw = r.w-mean;
    float ss = dx*dx + dy*dy + dz*dz + dw*dw;
    ss = block_reduce(ss, sred, false);
    float inv = rsqrtf(ss*(1.0f/DIM) + 1e-5f);
    float4 gv = ((const float4*)g2)[t];
    float4 bv = ((const float4*)b2)[t];
    float4 o;
    o.x = f2tf32f(dx*inv*gv.x + bv.x);  o.y = f2tf32f(dy*inv*gv.y + bv.y);
    o.z = f2tf32f(dz*inv*gv.z + bv.z);  o.w = f2tf32f(dw*inv*gv.w + bv.w);
    ((float4*)(g_t + (size_t)m*DIM))[t] = o;
}

/* ------------------------------------------------------------------ */
__global__ void final_kernel(float* __restrict__ out) {
    int m = blockIdx.x, t = threadIdx.x;
    float4 r  = ((const float4*)(g_resid + (size_t)m*DIM))[t];
    float4 mm = ((const float4*)(g_mlp   + (size_t)m*DIM))[t];
    float4 o = make_float4(r.x+mm.x, r.y+mm.y, r.z+mm.z, r.w+mm.w);
    float* dst = (m < 128) ? (out + (size_t)m*DIM)
                           : (out + 128*DIM + (size_t)(m-128)*DIM);
    ((float4*)dst)[t] = o;
}

/* ------------------------------------------------------------------ */
extern "C" void kernel_launch(void* const* d_in, const int* in_sizes, int n_in,
                              void* d_out, int out_size) {
    const float* x         = (const float*)d_in[0];
    const float* mask      = (const float*)d_in[1];
    const float* in_proj_w = (const float*)d_in[5];
    const float* in_proj_b = (const float*)d_in[6];
    const float* out_w     = (const float*)d_in[7];
    const float* out_b     = (const float*)d_in[8];
    const float* ln1_g     = (const float*)d_in[9];
    const float* ln1_b     = (const float*)d_in[10];
    const float* ln2_g     = (const float*)d_in[11];
    const float* ln2_b     = (const float*)d_in[12];
    const float* fc_w      = (const float*)d_in[13];
    const float* fc_b      = (const float*)d_in[14];
    const float* proj_w    = (const float*)d_in[15];
    const float* proj_b    = (const float*)d_in[16];

    float *ph, *pkv, *pattout, *pproj, *pt, *pfc, *pmlp;
    float *pwkv, *pwout, *pwfc, *pwproj;
    cudaGetSymbolAddress((void**)&ph,      g_h);
    cudaGetSymbolAddress((void**)&pkv,     g_kv);
    cudaGetSymbolAddress((void**)&pattout, g_attout);
    cudaGetSymbolAddress((void**)&pproj,   g_proj);
    cudaGetSymbolAddress((void**)&pt,      g_t);
    cudaGetSymbolAddress((void**)&pfc,     g_fc);
    cudaGetSymbolAddress((void**)&pmlp,    g_mlp);
    cudaGetSymbolAddress((void**)&pwkv,    g_wkv);
    cudaGetSymbolAddress((void**)&pwout,   g_wout);
    cudaGetSymbolAddress((void**)&pwfc,    g_wfc);
    cudaGetSymbolAddress((void**)&pwproj,  g_wproj);

    const int GEMM_SMEM = 2*2*TILE_F*4;
    cudaFuncSetAttribute(gemm_tc<0,0>, cudaFuncAttributeMaxDynamicSharedMemorySize, GEMM_SMEM);
    cudaFuncSetAttribute(gemm_tc<1,1>, cudaFuncAttributeMaxDynamicSharedMemorySize, GEMM_SMEM);
    cudaFuncSetAttribute(gemm_big, cudaFuncAttributeMaxDynamicSharedMemorySize, BIG_SMEM);
    cudaFuncSetAttribute(softmax_av_kernel, cudaFuncAttributeMaxDynamicSharedMemorySize, 58080);

    /* 1-4. weight tf32 rounding */
    cvt_tf32_kernel<<<(2048*1024/4 + 255)/256, 256>>>(in_proj_w + 1024*1024, pwkv, 2048*1024/4);
    cvt_tf32_kernel<<<(1024*1024/4 + 255)/256, 256>>>(out_w, pwout, 1024*1024/4);
    cvt_tf32_kernel<<<(4*1024*1024/4 + 255)/256, 256>>>(fc_w, pwfc, 4*1024*1024/4);
    cvt_tf32_kernel<<<(4*1024*1024/4 + 255)/256, 256>>>(proj_w, pwproj, 4*1024*1024/4);

    /* 5. LN1 over all tokens (tf32-rounded out) */
    ln1_kernel<<<NROWS, 256>>>(x, ln1_g, ln1_b, ph);

    /* 6. K,V projection: [4616,1024] x [2048,1024]^T on big-tile GEMM */
    gemm_big<<<dim3(2048/256, (NROWS+127)/128), 256, BIG_SMEM>>>(
        ph, pwkv, in_proj_b + 1024, pkv, NROWS, 2048, 1024);

    /* 7. Q projection (CLS rows, fp32) */
    q_kernel<<<1024, 256>>>(in_proj_w, in_proj_b);

    /* 8. attn logits */
    attn_kernel<<<BATCH*NHEAD, 128>>>();

    /* 9. 17-way softmax + P@V */
    softmax_av_kernel<<<BATCH*NHEAD, 256, 58080>>>(mask);

    /* 10. output projection (136 rows) */
    gemm_tc<0,0><<<dim3(1024/128, 2), 256, GEMM_SMEM>>>(
        pattout, pwout, out_b, pproj, MROW, 1024, 1024);

    /* 11. residual + LN2 */
    resid_ln2_kernel<<<MROW, 256>>>(x, ln2_g, ln2_b);

    /* 12. MLP fc + QuickGELU */
    gemm_tc<1,1><<<dim3(4096/128, 2), 256, GEMM_SMEM>>>(
        pt, pwfc, fc_b, pfc, MROW, 4096, 1024);

    /* 13. MLP proj */
    gemm_tc<0,0><<<dim3(1024/128, 2), 256, GEMM_SMEM>>>(
        pfc, pwproj, proj_b, pmlp, MROW, 1024, 4096);

    /* 14. residual + scatter to output */
    final_kernel<<<MROW, 256>>>((float*)d_out);
}

// round 6
// speedup vs baseline: 5.7824x; 1.3740x over previous
#include <cuda_runtime.h>
#include <math.h>
#include <stdint.h>

#define S_LEN 577
#define BATCH 8
#define DIM   1024
#define NHEAD 16
#define HD    64
#define NBOX  16
#define NROWS (S_LEN*BATCH)   /* 4616 */
#define MROW  136             /* 128 mask rows + 8 cls rows */

/* ------------------------------------------------------------------ */
/* scratch (device globals; no allocation allowed)                    */
/* ------------------------------------------------------------------ */
__device__ float g_h[NROWS*DIM];          // LN1 output (tf32-rounded)
__device__ float g_kv[NROWS*2048];        // [row, 0:1024]=k, [1024:2048]=v
__device__ float g_q0[BATCH*DIM];
__device__ float g_attn[BATCH*NHEAD*S_LEN];
__device__ float g_attout[MROW*DIM];      // tf32-rounded
__device__ float g_resid[MROW*DIM];
__device__ float g_t[MROW*DIM];           // tf32-rounded
__device__ float g_fc[MROW*4096];         // tf32-rounded
__device__ float g_part[4*MROW*DIM];      // split-K partial sums

/* ------------------------------------------------------------------ */
__device__ __forceinline__ float block_reduce(float v, float* sm, bool is_max) {
    int lane = threadIdx.x & 31, wid = threadIdx.x >> 5;
    #pragma unroll
    for (int o = 16; o; o >>= 1) {
        float u = __shfl_down_sync(0xffffffffu, v, o);
        v = is_max ? fmaxf(v, u) : v + u;
    }
    if (lane == 0) sm[wid] = v;
    __syncthreads();
    int nw = blockDim.x >> 5;
    if (wid == 0) {
        v = (lane < nw) ? sm[lane] : (is_max ? -3.0e38f : 0.0f);
        #pragma unroll
        for (int o = 16; o; o >>= 1) {
            float u = __shfl_down_sync(0xffffffffu, v, o);
            v = is_max ? fmaxf(v, u) : v + u;
        }
        if (lane == 0) sm[0] = v;
    }
    __syncthreads();
    float r = sm[0];
    __syncthreads();
    return r;
}

__device__ __forceinline__ float f2tf32f(float f) {
    uint32_t u;
    asm("cvt.rna.tf32.f32 %0, %1;" : "=r"(u) : "f"(f));
    return __uint_as_float(u);
}

__device__ __forceinline__ void cp_async16(uint32_t saddr, const void* gaddr, int src_size) {
    asm volatile("cp.async.cg.shared.global [%0], [%1], 16, %2;\n"
                 :: "r"(saddr), "l"(gaddr), "r"(src_size));
}

__device__ __forceinline__ uint32_t smem_u32(const void* p) {
    return (uint32_t)__cvta_generic_to_shared(p);
}

/* ------------------------------------------------------------------ */
/* LayerNorm over 1024 cols, one block (256 thr) per row. out tf32.   */
/* ------------------------------------------------------------------ */
__global__ void ln1_kernel(const float* __restrict__ x,
                           const float* __restrict__ g,
                           const float* __restrict__ b,
                           float* __restrict__ out) {
    __shared__ float sred[32];
    int row = blockIdx.x, t = threadIdx.x;
    float4 v = ((const float4*)(x + (size_t)row*DIM))[t];
    float s = v.x + v.y + v.z + v.w;
    s = block_reduce(s, sred, false);
    float mean = s * (1.0f/DIM);
    float dx = v.x-mean, dy = v.y-mean, dz = v.z-mean, dw = v.w-mean;
    float ss = dx*dx + dy*dy + dz*dz + dw*dw;
    ss = block_reduce(ss, sred, false);
    float inv = rsqrtf(ss*(1.0f/DIM) + 1e-5f);
    float4 gv = ((const float4*)g)[t];
    float4 bv = ((const float4*)b)[t];
    float4 o;
    o.x = f2tf32f(dx*inv*gv.x + bv.x);  o.y = f2tf32f(dy*inv*gv.y + bv.y);
    o.z = f2tf32f(dz*inv*gv.z + bv.z);  o.w = f2tf32f(dw*inv*gv.w + bv.w);
    ((float4*)(out + (size_t)row*DIM))[t] = o;
}

/* ------------------------------------------------------------------ */
/* tf32 GEMM: 128 threads, BM=BN=128, BK=32, 4 warps (2x2),           */
/* warp tile 64x64 (4x8 m16n8k8), cp.async double-buffered, 2 CTA/SM. */
/* SPLITK>1: blockIdx.z = k-chunk; raw partials to C + z*M*N, no bias */
/* ACT: 1 = QuickGELU (only when SPLITK==1). RND: round out to tf32.  */
/* ------------------------------------------------------------------ */
#define TSTRIDE 36
#define TILE_F (128*TSTRIDE)
#define GEMM_SMEM (2*2*TILE_F*4)   /* 73728 B */

template<int ACT, int RND, int SPLITK>
__global__ void __launch_bounds__(128, 2)
gemm_w64(const float* __restrict__ A,
         const float* __restrict__ W,
         const float* __restrict__ bias,
         float* __restrict__ C,
         int M, int N, int K) {
    extern __shared__ float smemf[];
    float* Abuf = smemf;                 // [2][128][36]
    float* Bbuf = smemf + 2*TILE_F;      // [2][128][36]
    uint32_t Abase = smem_u32(Abuf);
    uint32_t Bbase = smem_u32(Bbuf);

    int tid = threadIdx.x;
    int warp = tid >> 5, lane = tid & 31;
    int wm = warp & 1, wn = warp >> 1;          // 2 x 2 warps
    int g = lane >> 2, c = lane & 3;
    int m0 = blockIdx.y * 128, n0 = blockIdx.x * 128;
    int Kc = K / SPLITK;
    int kbase = blockIdx.z * Kc;

    float acc[4][8][4];
    #pragma unroll
    for (int i = 0; i < 4; i++)
        #pragma unroll
        for (int j = 0; j < 8; j++)
            #pragma unroll
            for (int r = 0; r < 4; r++) acc[i][j][r] = 0.0f;

    const int NIT = Kc >> 5;

    auto load_tile = [&](int s, int k0) {
        #pragma unroll
        for (int i = 0; i < 8; i++) {
            int ch = tid + i*128;                // 0..1023
            int m = ch >> 3, kq = ch & 7;
            const float* ga = A + (size_t)(m0 + m)*K + k0 + kq*4;
            int sz = (m0 + m < M) ? 16 : 0;
            cp_async16(Abase + (uint32_t)((s*TILE_F + m*TSTRIDE + kq*4)*4), ga, sz);
            const float* gb = W + (size_t)(n0 + m)*K + k0 + kq*4;
            cp_async16(Bbase + (uint32_t)((s*TILE_F + m*TSTRIDE + kq*4)*4), gb, 16);
        }
    };

    load_tile(0, kbase);
    asm volatile("cp.async.commit_group;\n");

    int buf = 0;
    for (int it = 0; it < NIT; it++) {
        if (it + 1 < NIT) load_tile(buf ^ 1, kbase + ((it + 1) << 5));
        asm volatile("cp.async.commit_group;\n");
        asm volatile("cp.async.wait_group 1;\n");
        __syncthreads();

        const float* As_s = Abuf + buf*TILE_F;
        const float* Bs_s = Bbuf + buf*TILE_F;
        #pragma unroll
        for (int kk = 0; kk < 32; kk += 8) {
            uint32_t a[4][4];
            #pragma unroll
            for (int i = 0; i < 4; i++) {
                int mr = (wm*64 + i*16 + g) * TSTRIDE;
                a[i][0] = __float_as_uint(As_s[mr             + kk + c    ]);
                a[i][1] = __float_as_uint(As_s[mr + 8*TSTRIDE + kk + c    ]);
                a[i][2] = __float_as_uint(As_s[mr             + kk + c + 4]);
                a[i][3] = __float_as_uint(As_s[mr + 8*TSTRIDE + kk + c + 4]);
            }
            uint32_t b[8][2];
            #pragma unroll
            for (int j = 0; j < 8; j++) {
                int nc = (wn*64 + j*8 + g) * TSTRIDE;
                b[j][0] = __float_as_uint(Bs_s[nc + kk + c    ]);
                b[j][1] = __float_as_uint(Bs_s[nc + kk + c + 4]);
            }
            #pragma unroll
            for (int i = 0; i < 4; i++)
                #pragma unroll
                for (int j = 0; j < 8; j++) {
                    asm volatile(
                        "mma.sync.aligned.m16n8k8.row.col.f32.tf32.tf32.f32 "
                        "{%0,%1,%2,%3}, {%4,%5,%6,%7}, {%8,%9}, {%0,%1,%2,%3};\n"
                        : "+f"(acc[i][j][0]), "+f"(acc[i][j][1]),
                          "+f"(acc[i][j][2]), "+f"(acc[i][j][3])
                        : "r"(a[i][0]), "r"(a[i][1]), "r"(a[i][2]), "r"(a[i][3]),
                          "r"(b[j][0]), "r"(b[j][1]));
                }
        }
        __syncthreads();
        buf ^= 1;
    }

    float* Co = (SPLITK > 1) ? (C + (size_t)blockIdx.z * M * N) : C;
    #pragma unroll
    for (int i = 0; i < 4; i++) {
        int mA = m0 + wm*64 + i*16 + g;
        int mB = mA + 8;
        #pragma unroll
        for (int j = 0; j < 8; j++) {
            int n = n0 + wn*64 + j*8 + 2*c;
            float b0 = 0.0f, b1 = 0.0f;
            if (SPLITK == 1) { b0 = bias[n]; b1 = bias[n+1]; }
            if (mA < M) {
                float v0 = acc[i][j][0] + b0;
                float v1 = acc[i][j][1] + b1;
                if (ACT == 1) {
                    v0 = v0 / (1.0f + expf(-1.702f * v0));
                    v1 = v1 / (1.0f + expf(-1.702f * v1));
                }
                if (RND == 1) { v0 = f2tf32f(v0); v1 = f2tf32f(v1); }
                *(float2*)(Co + (size_t)mA*N + n) = make_float2(v0, v1);
            }
            if (mB < M) {
                float v0 = acc[i][j][2] + b0;
                float v1 = acc[i][j][3] + b1;
                if (ACT == 1) {
                    v0 = v0 / (1.0f + expf(-1.702f * v0));
                    v1 = v1 / (1.0f + expf(-1.702f * v1));
                }
                if (RND == 1) { v0 = f2tf32f(v0); v1 = f2tf32f(v1); }
                *(float2*)(Co + (size_t)mB*N + n) = make_float2(v0, v1);
            }
        }
    }
}

/* ------------------------------------------------------------------ */
/* Q projection, CLS rows only: warp-per-output fp32                  */
/* ------------------------------------------------------------------ */
__global__ void q_kernel(const float* __restrict__ w, const float* __restrict__ b) {
    int gw = (blockIdx.x * blockDim.x + threadIdx.x) >> 5;
    int lane = threadIdx.x & 31;
    int m = gw >> 10, n = gw & 1023;
    const float4* hr = (const float4*)(g_h + (size_t)m*DIM);
    const float4* wr = (const float4*)(w + (size_t)n*DIM);
    float acc = 0.0f;
    #pragma unroll
    for (int i = 0; i < 8; i++) {
        float4 a = hr[lane + i*32], ww = wr[lane + i*32];
        acc += a.x*ww.x + a.y*ww.y + a.z*ww.z + a.w*ww.w;
    }
    #pragma unroll
    for (int o = 16; o; o >>= 1) acc += __shfl_down_sync(0xffffffffu, acc, o);
    if (lane == 0) g_q0[m*DIM + n] = acc + b[n];
}

/* ------------------------------------------------------------------ */
__global__ void attn_kernel() {
    int bh = blockIdx.x;
    int b = bh >> 4, h = bh & 15;
    __shared__ float q[HD];
    int t = threadIdx.x;
    if (t < HD) q[t] = g_q0[b*DIM + h*HD + t] * 0.125f;
    __syncthreads();
    for (int s = t; s < S_LEN; s += 128) {
        const float4* kr = (const float4*)(g_kv + (size_t)(s*BATCH + b)*2048 + h*HD);
        float acc = 0.0f;
        #pragma unroll
        for (int i = 0; i < 16; i++) {
            float4 kv4 = kr[i];
            acc += kv4.x*q[i*4+0] + kv4.y*q[i*4+1] + kv4.z*q[i*4+2] + kv4.w*q[i*4+3];
        }
        g_attn[bh*S_LEN + s] = acc;
    }
}

/* ------------------------------------------------------------------ */
__global__ void softmax_av_kernel(const float* __restrict__ mask) {
    extern __shared__ float sm[];
    float* sm_p    = sm;
    float* sm_attn = sm + 9812;
    float* sm_v    = sm + 10392;
    float* sm_red  = sm + 14488;
    int bh = blockIdx.x, b = bh >> 4, h = bh & 15;
    int t = threadIdx.x;

    for (int s = t; s < S_LEN; s += 256) sm_attn[s] = g_attn[bh*S_LEN + s];
    __syncthreads();

    for (int var = 0; var < 17; var++) {
        float* pr = sm_p + var * S_LEN;
        const float* mrow = (var < 16)
            ? (mask + (size_t)((b*NBOX + var)*NHEAD + h) * S_LEN) : (const float*)0;
        float mx = -3.0e38f;
        for (int s = t; s < S_LEN; s += 256) {
            float a = sm_attn[s] + (mrow ? mrow[s] : 0.0f);
            pr[s] = a;
            mx = fmaxf(mx, a);
        }
        mx = block_reduce(mx, sm_red, true);
        float sum = 0.0f;
        for (int s = t; s < S_LEN; s += 256) {
            float e = expf(pr[s] - mx);
            pr[s] = e;
            sum += e;
        }
        sum = block_reduce(sum, sm_red, false);
        float inv = 1.0f / sum;
        for (int s = t; s < S_LEN; s += 256) pr[s] *= inv;
        __syncthreads();
    }

    int e = t & 63, grp = t >> 6;
    float acc[5] = {0.f, 0.f, 0.f, 0.f, 0.f};
    for (int s0 = 0; s0 < S_LEN; s0 += 64) {
        __syncthreads();
        #pragma unroll
        for (int it = 0; it < 4; it++) {
            int idx = t + it * 256;
            int r = idx >> 4, c4 = (idx & 15) << 2;
            int s = s0 + r;
            float4 vv = make_float4(0.f, 0.f, 0.f, 0.f);
            if (s < S_LEN)
                vv = *(const float4*)(g_kv + (size_t)(s*BATCH + b)*2048 + 1024 + h*HD + c4);
            *(float4*)(sm_v + r*64 + c4) = vv;
        }
        __syncthreads();
        int smax = min(64, S_LEN - s0);
        for (int r = 0; r < smax; r++) {
            float vv = sm_v[r*64 + e];
            #pragma unroll
            for (int i = 0; i < 4; i++)
                acc[i] += sm_p[(grp + 4*i)*S_LEN + s0 + r] * vv;
            if (grp == 0)
                acc[4] += sm_p[16*S_LEN + s0 + r] * vv;
        }
    }
    int col = h*HD + e;
    #pragma unroll
    for (int i = 0; i < 4; i++) {
        int var = grp + 4*i;
        g_attout[(size_t)(b*NBOX + var)*DIM + col] = f2tf32f(acc[i]);
    }
    if (grp == 0)
        g_attout[(size_t)(128 + b)*DIM + col] = f2tf32f(acc[4]);
}

/* ------------------------------------------------------------------ */
/* resid = x0 + (part0+part1+out_b); t = LN2(resid) (tf32-rounded)    */
/* ------------------------------------------------------------------ */
__global__ void resid_ln2_kernel(const float* __restrict__ x,
                                 const float* __restrict__ ob,
                                 const float* __restrict__ g2,
                                 const float* __restrict__ b2) {
    __shared__ float sred[32];
    int m = blockIdx.x, t = threadIdx.x;
    int b = (m < 128) ? (m >> 4) : (m - 128);
    float4 xv = ((const float4*)(x + (size_t)b*DIM))[t];
    float4 p0 = ((const float4*)(g_part + (size_t)m*DIM))[t];
    float4 p1 = ((const float4*)(g_part + (size_t)(MROW + m)*DIM))[t];
    float4 bo = ((const float4*)ob)[t];
    float4 r = make_float4(xv.x + p0.x + p1.x + bo.x,
                           xv.y + p0.y + p1.y + bo.y,
                           xv.z + p0.z + p1.z + bo.z,
                           xv.w + p0.w + p1.w + bo.w);
    ((float4*)(g_resid + (size_t)m*DIM))[t] = r;
    float s = r.x + r.y + r.z + r.w;
    s = block_reduce(s, sred, false);
    float mean = s * (1.0f/DIM);
    float dx = r.x-mean, dy = r.y-mean, dz = r.z-mean, dw = r.w-mean;
    float ss = dx*dx + dy*dy + dz*dz + dw*dw;
    ss = block_reduce(ss, sred, false);
    float inv = rsqrtf(ss*(1.0f/DIM) + 1e-5f);
    float4 gv = ((const float4*)g2)[t];
    float4 bv = ((const float4*)b2)[t];
    float4 o;
    o.x = f2tf32f(dx*inv*gv.x + bv.x);  o.y = f2tf32f(dy*inv*gv.y + bv.y);
    o.z = f2tf32f(dz*inv*gv.z + bv.z);  o.w = f2tf32f(dw*inv*gv.w + bv.w);
    ((float4*)(g_t + (size_t)m*DIM))[t] = o;
}

/* ------------------------------------------------------------------ */
/* final = resid + (part0..3 + proj_b); scatter to output             */
/* ------------------------------------------------------------------ */
__global__ void final_kernel(const float* __restrict__ pb, float* __restrict__ out) {
    int m = blockIdx.x, t = threadIdx.x;
    float4 r  = ((const float4*)(g_resid + (size_t)m*DIM))[t];
    float4 p0 = ((const float4*)(g_part + (size_t)m*DIM))[t];
    float4 p1 = ((const float4*)(g_part + (size_t)(MROW + m)*DIM))[t];
    float4 p2 = ((const float4*)(g_part + (size_t)(2*MROW + m)*DIM))[t];
    float4 p3 = ((const float4*)(g_part + (size_t)(3*MROW + m)*DIM))[t];
    float4 bv = ((const float4*)pb)[t];
    float4 o = make_float4(r.x + p0.x + p1.x + p2.x + p3.x + bv.x,
                           r.y + p0.y + p1.y + p2.y + p3.y + bv.y,
                           r.z + p0.z + p1.z + p2.z + p3.z + bv.z,
                           r.w + p0.w + p1.w + p2.w + p3.w + bv.w);
    float* dst = (m < 128) ? (out + (size_t)m*DIM)
                           : (out + 128*DIM + (size_t)(m-128)*DIM);
    ((float4*)dst)[t] = o;
}

/* ------------------------------------------------------------------ */
extern "C" void kernel_launch(void* const* d_in, const int* in_sizes, int n_in,
                              void* d_out, int out_size) {
    const float* x         = (const float*)d_in[0];
    const float* mask      = (const float*)d_in[1];
    const float* in_proj_w = (const float*)d_in[5];
    const float* in_proj_b = (const float*)d_in[6];
    const float* out_w     = (const float*)d_in[7];
    const float* out_b     = (const float*)d_in[8];
    const float* ln1_g     = (const float*)d_in[9];
    const float* ln1_b     = (const float*)d_in[10];
    const float* ln2_g     = (const float*)d_in[11];
    const float* ln2_b     = (const float*)d_in[12];
    const float* fc_w      = (const float*)d_in[13];
    const float* fc_b      = (const float*)d_in[14];
    const float* proj_w    = (const float*)d_in[15];
    const float* proj_b    = (const float*)d_in[16];

    float *ph, *pkv, *pattout, *pt, *pfc, *ppart;
    cudaGetSymbolAddress((void**)&ph,      g_h);
    cudaGetSymbolAddress((void**)&pkv,     g_kv);
    cudaGetSymbolAddress((void**)&pattout, g_attout);
    cudaGetSymbolAddress((void**)&pt,      g_t);
    cudaGetSymbolAddress((void**)&pfc,     g_fc);
    cudaGetSymbolAddress((void**)&ppart,   g_part);

    cudaFuncSetAttribute(gemm_w64<0,0,1>, cudaFuncAttributeMaxDynamicSharedMemorySize, GEMM_SMEM);
    cudaFuncSetAttribute(gemm_w64<0,0,2>, cudaFuncAttributeMaxDynamicSharedMemorySize, GEMM_SMEM);
    cudaFuncSetAttribute(gemm_w64<0,0,4>, cudaFuncAttributeMaxDynamicSharedMemorySize, GEMM_SMEM);
    cudaFuncSetAttribute(gemm_w64<1,1,1>, cudaFuncAttributeMaxDynamicSharedMemorySize, GEMM_SMEM);
    cudaFuncSetAttribute(softmax_av_kernel, cudaFuncAttributeMaxDynamicSharedMemorySize, 58080);

    /* 1. LN1 over all tokens (tf32-rounded out) */
    ln1_kernel<<<NROWS, 256>>>(x, ln1_g, ln1_b, ph);

    /* 2. K,V projection: [4616,1024] x [2048,1024]^T (raw fp32 W) */
    gemm_w64<0,0,1><<<dim3(2048/128, (NROWS+127)/128), 128, GEMM_SMEM>>>(
        ph, in_proj_w + 1024*1024, in_proj_b + 1024, pkv, NROWS, 2048, 1024);

    /* 3. Q projection (CLS rows, fp32) */
    q_kernel<<<1024, 256>>>(in_proj_w, in_proj_b);

    /* 4. attn logits */
    attn_kernel<<<BATCH*NHEAD, 128>>>();

    /* 5. 17-way softmax + P@V */
    softmax_av_kernel<<<BATCH*NHEAD, 256, 58080>>>(mask);

    /* 6. output projection (136 rows), split-K 2 -> partials */
    gemm_w64<0,0,2><<<dim3(1024/128, 2, 2), 128, GEMM_SMEM>>>(
        pattout, out_w, out_b, ppart, MROW, 1024, 1024);

    /* 7. residual + out_b + LN2 (reduces 2 partials) */
    resid_ln2_kernel<<<MROW, 256>>>(x, out_b, ln2_g, ln2_b);

    /* 8. MLP fc + QuickGELU */
    gemm_w64<1,1,1><<<dim3(4096/128, 2), 128, GEMM_SMEM>>>(
        pt, fc_w, fc_b, pfc, MROW, 4096, 1024);

    /* 9. MLP proj, split-K 4 -> partials */
    gemm_w64<0,0,4><<<dim3(1024/128, 2, 4), 128, GEMM_SMEM>>>(
        pfc, proj_w, proj_b, ppart, MROW, 1024, 4096);

    /* 10. residual + proj_b + scatter (reduces 4 partials) */
    final_kernel<<<MROW, 256>>>(proj_b, (float*)d_out);
}

// round 7
// speedup vs baseline: 6.8018x; 1.1763x over previous
#include <cuda_runtime.h>
#include <math.h>
#include <stdint.h>

#define S_LEN 577
#define BATCH 8
#define DIM   1024
#define NHEAD 16
#define HD    64
#define NBOX  16
#define NROWS (S_LEN*BATCH)   /* 4616 */
#define MROW  136             /* 128 mask rows + 8 cls rows */

/* ------------------------------------------------------------------ */
/* scratch (device globals; no allocation allowed)                    */
/* ------------------------------------------------------------------ */
__device__ float g_h[NROWS*DIM];          // LN1 output (tf32-rounded)
__device__ float g_kv[NROWS*2048];        // [row, 0:1024]=k, [1024:2048]=v
__device__ float g_attout[MROW*DIM];      // tf32-rounded
__device__ float g_resid[MROW*DIM];
__device__ float g_t[MROW*DIM];           // tf32-rounded
__device__ float g_fc[MROW*4096];         // tf32-rounded
__device__ float g_part[2*MROW*4096];     // split-K partials (max use: fc k2)

/* ------------------------------------------------------------------ */
__device__ __forceinline__ float block_reduce(float v, float* sm, bool is_max) {
    int lane = threadIdx.x & 31, wid = threadIdx.x >> 5;
    #pragma unroll
    for (int o = 16; o; o >>= 1) {
        float u = __shfl_down_sync(0xffffffffu, v, o);
        v = is_max ? fmaxf(v, u) : v + u;
    }
    if (lane == 0) sm[wid] = v;
    __syncthreads();
    int nw = blockDim.x >> 5;
    if (wid == 0) {
        v = (lane < nw) ? sm[lane] : (is_max ? -3.0e38f : 0.0f);
        #pragma unroll
        for (int o = 16; o; o >>= 1) {
            float u = __shfl_down_sync(0xffffffffu, v, o);
            v = is_max ? fmaxf(v, u) : v + u;
        }
        if (lane == 0) sm[0] = v;
    }
    __syncthreads();
    float r = sm[0];
    __syncthreads();
    return r;
}

__device__ __forceinline__ float f2tf32f(float f) {
    uint32_t u;
    asm("cvt.rna.tf32.f32 %0, %1;" : "=r"(u) : "f"(f));
    return __uint_as_float(u);
}

__device__ __forceinline__ void cp_async16(uint32_t saddr, const void* gaddr, int src_size) {
    asm volatile("cp.async.cg.shared.global [%0], [%1], 16, %2;\n"
                 :: "r"(saddr), "l"(gaddr), "r"(src_size));
}

__device__ __forceinline__ uint32_t smem_u32(const void* p) {
    return (uint32_t)__cvta_generic_to_shared(p);
}

/* ------------------------------------------------------------------ */
/* LayerNorm over 1024 cols, one block (256 thr) per row. out tf32.   */
/* ------------------------------------------------------------------ */
__global__ void ln1_kernel(const float* __restrict__ x,
                           const float* __restrict__ g,
                           const float* __restrict__ b,
                           float* __restrict__ out) {
    __shared__ float sred[32];
    int row = blockIdx.x, t = threadIdx.x;
    float4 v = ((const float4*)(x + (size_t)row*DIM))[t];
    float s = v.x + v.y + v.z + v.w;
    s = block_reduce(s, sred, false);
    float mean = s * (1.0f/DIM);
    float dx = v.x-mean, dy = v.y-mean, dz = v.z-mean, dw = v.w-mean;
    float ss = dx*dx + dy*dy + dz*dz + dw*dw;
    ss = block_reduce(ss, sred, false);
    float inv = rsqrtf(ss*(1.0f/DIM) + 1e-5f);
    float4 gv = ((const float4*)g)[t];
    float4 bv = ((const float4*)b)[t];
    float4 o;
    o.x = f2tf32f(dx*inv*gv.x + bv.x);  o.y = f2tf32f(dy*inv*gv.y + bv.y);
    o.z = f2tf32f(dz*inv*gv.z + bv.z);  o.w = f2tf32f(dw*inv*gv.w + bv.w);
    ((float4*)(out + (size_t)row*DIM))[t] = o;
}

/* ------------------------------------------------------------------ */
/* tf32 GEMM: 128 threads, BM=BN=128, BK=32, 4 warps (2x2),           */
/* warp tile 64x64, cp.async double-buffered, 2 CTA/SM.               */
/* SPLITK>1: blockIdx.z = k-chunk; raw partials to C + z*M*N, no bias */
/* ACT: 1 = QuickGELU (SPLITK==1 only). RND: round out to tf32.       */
/* ------------------------------------------------------------------ */
#define TSTRIDE 36
#define TILE_F (128*TSTRIDE)
#define GEMM_SMEM (2*2*TILE_F*4)   /* 73728 B */

template<int ACT, int RND, int SPLITK>
__global__ void __launch_bounds__(128, 2)
gemm_w64(const float* __restrict__ A,
         const float* __restrict__ W,
         const float* __restrict__ bias,
         float* __restrict__ C,
         int M, int N, int K) {
    extern __shared__ float smemf[];
    float* Abuf = smemf;                 // [2][128][36]
    float* Bbuf = smemf + 2*TILE_F;      // [2][128][36]
    uint32_t Abase = smem_u32(Abuf);
    uint32_t Bbase = smem_u32(Bbuf);

    int tid = threadIdx.x;
    int warp = tid >> 5, lane = tid & 31;
    int wm = warp & 1, wn = warp >> 1;          // 2 x 2 warps
    int g = lane >> 2, c = lane & 3;
    int m0 = blockIdx.y * 128, n0 = blockIdx.x * 128;
    int Kc = K / SPLITK;
    int kbase = blockIdx.z * Kc;

    float acc[4][8][4];
    #pragma unroll
    for (int i = 0; i < 4; i++)
        #pragma unroll
        for (int j = 0; j < 8; j++)
            #pragma unroll
            for (int r = 0; r < 4; r++) acc[i][j][r] = 0.0f;

    const int NIT = Kc >> 5;

    auto load_tile = [&](int s, int k0) {
        #pragma unroll
        for (int i = 0; i < 8; i++) {
            int ch = tid + i*128;                // 0..1023
            int m = ch >> 3, kq = ch & 7;
            const float* ga = A + (size_t)(m0 + m)*K + k0 + kq*4;
            int sz = (m0 + m < M) ? 16 : 0;
            cp_async16(Abase + (uint32_t)((s*TILE_F + m*TSTRIDE + kq*4)*4), ga, sz);
            const float* gb = W + (size_t)(n0 + m)*K + k0 + kq*4;
            cp_async16(Bbase + (uint32_t)((s*TILE_F + m*TSTRIDE + kq*4)*4), gb, 16);
        }
    };

    load_tile(0, kbase);
    asm volatile("cp.async.commit_group;\n");

    int buf = 0;
    for (int it = 0; it < NIT; it++) {
        if (it + 1 < NIT) load_tile(buf ^ 1, kbase + ((it + 1) << 5));
        asm volatile("cp.async.commit_group;\n");
        asm volatile("cp.async.wait_group 1;\n");
        __syncthreads();

        const float* As_s = Abuf + buf*TILE_F;
        const float* Bs_s = Bbuf + buf*TILE_F;
        #pragma unroll
        for (int kk = 0; kk < 32; kk += 8) {
            uint32_t a[4][4];
            #pragma unroll
            for (int i = 0; i < 4; i++) {
                int mr = (wm*64 + i*16 + g) * TSTRIDE;
                a[i][0] = __float_as_uint(As_s[mr             + kk + c    ]);
                a[i][1] = __float_as_uint(As_s[mr + 8*TSTRIDE + kk + c    ]);
                a[i][2] = __float_as_uint(As_s[mr             + kk + c + 4]);
                a[i][3] = __float_as_uint(As_s[mr + 8*TSTRIDE + kk + c + 4]);
            }
            uint32_t b[8][2];
            #pragma unroll
            for (int j = 0; j < 8; j++) {
                int nc = (wn*64 + j*8 + g) * TSTRIDE;
                b[j][0] = __float_as_uint(Bs_s[nc + kk + c    ]);
                b[j][1] = __float_as_uint(Bs_s[nc + kk + c + 4]);
            }
            #pragma unroll
            for (int i = 0; i < 4; i++)
                #pragma unroll
                for (int j = 0; j < 8; j++) {
                    asm volatile(
                        "mma.sync.aligned.m16n8k8.row.col.f32.tf32.tf32.f32 "
                        "{%0,%1,%2,%3}, {%4,%5,%6,%7}, {%8,%9}, {%0,%1,%2,%3};\n"
                        : "+f"(acc[i][j][0]), "+f"(acc[i][j][1]),
                          "+f"(acc[i][j][2]), "+f"(acc[i][j][3])
                        : "r"(a[i][0]), "r"(a[i][1]), "r"(a[i][2]), "r"(a[i][3]),
                          "r"(b[j][0]), "r"(b[j][1]));
                }
        }
        __syncthreads();
        buf ^= 1;
    }

    float* Co = (SPLITK > 1) ? (C + (size_t)blockIdx.z * M * N) : C;
    #pragma unroll
    for (int i = 0; i < 4; i++) {
        int mA = m0 + wm*64 + i*16 + g;
        int mB = mA + 8;
        #pragma unroll
        for (int j = 0; j < 8; j++) {
            int n = n0 + wn*64 + j*8 + 2*c;
            float b0 = 0.0f, b1 = 0.0f;
            if (SPLITK == 1) { b0 = bias[n]; b1 = bias[n+1]; }
            if (mA < M) {
                float v0 = acc[i][j][0] + b0;
                float v1 = acc[i][j][1] + b1;
                if (ACT == 1) {
                    v0 = v0 / (1.0f + expf(-1.702f * v0));
                    v1 = v1 / (1.0f + expf(-1.702f * v1));
                }
                if (RND == 1) { v0 = f2tf32f(v0); v1 = f2tf32f(v1); }
                *(float2*)(Co + (size_t)mA*N + n) = make_float2(v0, v1);
            }
            if (mB < M) {
                float v0 = acc[i][j][2] + b0;
                float v1 = acc[i][j][3] + b1;
                if (ACT == 1) {
                    v0 = v0 / (1.0f + expf(-1.702f * v0));
                    v1 = v1 / (1.0f + expf(-1.702f * v1));
                }
                if (RND == 1) { v0 = f2tf32f(v0); v1 = f2tf32f(v1); }
                *(float2*)(Co + (size_t)mB*N + n) = make_float2(v0, v1);
            }
        }
    }
}

/* ------------------------------------------------------------------ */
/* Fused attention per (b,h): q proj (64 outs) + attn logits +        */
/* 17 softmax variants + P@V.  256 threads.                           */
/* smem floats: p 9812 | attn 580 | v 4096 | red 32(+pad 8) | h 1024  */
/* | q 64  => 15616 floats = 62464 B                                  */
/* ------------------------------------------------------------------ */
#define ATT_SMEM (15616*4)

__global__ void fused_attn_kernel(const float* __restrict__ mask,
                                  const float* __restrict__ wq,
                                  const float* __restrict__ bq) {
    extern __shared__ float sm[];
    float* sm_p    = sm;               // 17*577
    float* sm_attn = sm + 9812;        // 577
    float* sm_v    = sm + 10392;       // 64*64
    float* sm_red  = sm + 14488;       // 32 (+8 pad)
    float* sm_h    = sm + 14528;       // 1024
    float* sm_q    = sm + 15552;       // 64
    int bh = blockIdx.x, b = bh >> 4, h = bh & 15;
    int t = threadIdx.x;               // 256
    int warp = t >> 5, lane = t & 31;

    /* load LN1(x[0,b]) row (row index b: s=0 rows are 0..7) */
    ((float4*)sm_h)[t] = ((const float4*)(g_h + (size_t)b*DIM))[t];
    __syncthreads();

    /* q projection: warp w computes outputs e = w*8 .. w*8+7 */
    #pragma unroll
    for (int i = 0; i < 8; i++) {
        int e = warp*8 + i;
        const float4* wr = (const float4*)(wq + (size_t)(h*HD + e)*DIM);
        float acc = 0.0f;
        #pragma unroll
        for (int ii = 0; ii < 8; ii++) {
            float4 a = ((const float4*)sm_h)[lane + ii*32];
            float4 w4 = wr[lane + ii*32];
            acc += a.x*w4.x + a.y*w4.y + a.z*w4.z + a.w*w4.w;
        }
        #pragma unroll
        for (int o = 16; o; o >>= 1) acc += __shfl_down_sync(0xffffffffu, acc, o);
        if (lane == 0) sm_q[e] = (acc + bq[h*HD + e]) * 0.125f;
    }
    __syncthreads();

    /* attn logits: attn[s] = q . k[s,b,h,:] */
    for (int s = t; s < S_LEN; s += 256) {
        const float4* kr = (const float4*)(g_kv + (size_t)(s*BATCH + b)*2048 + h*HD);
        float acc = 0.0f;
        #pragma unroll
        for (int i = 0; i < 16; i++) {
            float4 kv4 = kr[i];
            acc += kv4.x*sm_q[i*4+0] + kv4.y*sm_q[i*4+1]
                 + kv4.z*sm_q[i*4+2] + kv4.w*sm_q[i*4+3];
        }
        sm_attn[s] = acc;
    }
    __syncthreads();

    /* 17 softmax variants */
    for (int var = 0; var < 17; var++) {
        float* pr = sm_p + var * S_LEN;
        const float* mrow = (var < 16)
            ? (mask + (size_t)((b*NBOX + var)*NHEAD + h) * S_LEN) : (const float*)0;
        float mx = -3.0e38f;
        for (int s = t; s < S_LEN; s += 256) {
            float a = sm_attn[s] + (mrow ? mrow[s] : 0.0f);
            pr[s] = a;
            mx = fmaxf(mx, a);
        }
        mx = block_reduce(mx, sm_red, true);
        float sum = 0.0f;
        for (int s = t; s < S_LEN; s += 256) {
            float e = expf(pr[s] - mx);
            pr[s] = e;
            sum += e;
        }
        sum = block_reduce(sum, sm_red, false);
        float inv = 1.0f / sum;
        for (int s = t; s < S_LEN; s += 256) pr[s] *= inv;
        __syncthreads();
    }

    /* P @ V with V staged through smem */
    int e = t & 63, grp = t >> 6;
    float acc[5] = {0.f, 0.f, 0.f, 0.f, 0.f};
    for (int s0 = 0; s0 < S_LEN; s0 += 64) {
        __syncthreads();
        #pragma unroll
        for (int it = 0; it < 4; it++) {
            int idx = t + it * 256;
            int r = idx >> 4, c4 = (idx & 15) << 2;
            int s = s0 + r;
            float4 vv = make_float4(0.f, 0.f, 0.f, 0.f);
            if (s < S_LEN)
                vv = *(const float4*)(g_kv + (size_t)(s*BATCH + b)*2048 + 1024 + h*HD + c4);
            *(float4*)(sm_v + r*64 + c4) = vv;
        }
        __syncthreads();
        int smax = min(64, S_LEN - s0);
        for (int r = 0; r < smax; r++) {
            float vv = sm_v[r*64 + e];
            #pragma unroll
            for (int i = 0; i < 4; i++)
                acc[i] += sm_p[(grp + 4*i)*S_LEN + s0 + r] * vv;
            if (grp == 0)
                acc[4] += sm_p[16*S_LEN + s0 + r] * vv;
        }
    }
    int col = h*HD + e;
    #pragma unroll
    for (int i = 0; i < 4; i++) {
        int var = grp + 4*i;
        g_attout[(size_t)(b*NBOX + var)*DIM + col] = f2tf32f(acc[i]);
    }
    if (grp == 0)
        g_attout[(size_t)(128 + b)*DIM + col] = f2tf32f(acc[4]);
}

/* ------------------------------------------------------------------ */
/* fc reduce: g_fc = tf32(gelu(part0 + part1 + fc_b)), N=4096         */
/* ------------------------------------------------------------------ */
__global__ void gelu_reduce_kernel(const float* __restrict__ fb) {
    int i = blockIdx.x * blockDim.x + threadIdx.x;   // float4 index
    if (i >= MROW*4096/4) return;
    int n4 = i & (4096/4 - 1);
    float4 p0 = ((const float4*)g_part)[i];
    float4 p1 = ((const float4*)g_part)[MROW*4096/4 + i];
    float4 bv = ((const float4*)fb)[n4];
    float v[4] = {p0.x+p1.x+bv.x, p0.y+p1.y+bv.y, p0.z+p1.z+bv.z, p0.w+p1.w+bv.w};
    float4 o;
    #pragma unroll
    for (int j = 0; j < 4; j++)
        v[j] = f2tf32f(v[j] / (1.0f + expf(-1.702f * v[j])));
    o.x = v[0]; o.y = v[1]; o.z = v[2]; o.w = v[3];
    ((float4*)g_fc)[i] = o;
}

/* ------------------------------------------------------------------ */
/* resid = x0 + (part0..3 + out_b); t = LN2(resid) (tf32-rounded)     */
/* ------------------------------------------------------------------ */
__global__ void resid_ln2_kernel(const float* __restrict__ x,
                                 const float* __restrict__ ob,
                                 const float* __restrict__ g2,
                                 const float* __restrict__ b2) {
    __shared__ float sred[32];
    int m = blockIdx.x, t = threadIdx.x;
    int b = (m < 128) ? (m >> 4) : (m - 128);
    float4 xv = ((const float4*)(x + (size_t)b*DIM))[t];
    float4 bo = ((const float4*)ob)[t];
    float rx = xv.x + bo.x, ry = xv.y + bo.y, rz = xv.z + bo.z, rw = xv.w + bo.w;
    #pragma unroll
    for (int z = 0; z < 4; z++) {
        float4 p = ((const float4*)(g_part + (size_t)(z*MROW + m)*DIM))[t];
        rx += p.x; ry += p.y; rz += p.z; rw += p.w;
    }
    float4 r = make_float4(rx, ry, rz, rw);
    ((float4*)(g_resid + (size_t)m*DIM))[t] = r;
    float s = r.x + r.y + r.z + r.w;
    s = block_reduce(s, sred, false);
    float mean = s * (1.0f/DIM);
    float dx = r.x-mean, dy = r.y-mean, dz = r.z-mean, dw = r.w-mean;
    float ss = dx*dx + dy*dy + dz*dz + dw*dw;
    ss = block_reduce(ss, sred, false);
    float inv = rsqrtf(ss*(1.0f/DIM) + 1e-5f);
    float4 gv = ((const float4*)g2)[t];
    float4 bv = ((const float4*)b2)[t];
    float4 o;
    o.x = f2tf32f(dx*inv*gv.x + bv.x);  o.y = f2tf32f(dy*inv*gv.y + bv.y);
    o.z = f2tf32f(dz*inv*gv.z + bv.z);  o.w = f2tf32f(dw*inv*gv.w + bv.w);
    ((float4*)(g_t + (size_t)m*DIM))[t] = o;
}

/* ------------------------------------------------------------------ */
/* final = resid + (part0..7 + proj_b); scatter to output             */
/* ------------------------------------------------------------------ */
__global__ void final_kernel(const float* __restrict__ pb, float* __restrict__ out) {
    int m = blockIdx.x, t = threadIdx.x;
    float4 r  = ((const float4*)(g_resid + (size_t)m*DIM))[t];
    float4 bv = ((const float4*)pb)[t];
    float ox = r.x + bv.x, oy = r.y + bv.y, oz = r.z + bv.z, ow = r.w + bv.w;
    #pragma unroll
    for (int z = 0; z < 8; z++) {
        float4 p = ((const float4*)(g_part + (size_t)(z*MROW + m)*DIM))[t];
        ox += p.x; oy += p.y; oz += p.z; ow += p.w;
    }
    float4 o = make_float4(ox, oy, oz, ow);
    float* dst = (m < 128) ? (out + (size_t)m*DIM)
                           : (out + 128*DIM + (size_t)(m-128)*DIM);
    ((float4*)dst)[t] = o;
}

/* ------------------------------------------------------------------ */
extern "C" void kernel_launch(void* const* d_in, const int* in_sizes, int n_in,
                              void* d_out, int out_size) {
    const float* x         = (const float*)d_in[0];
    const float* mask      = (const float*)d_in[1];
    const float* in_proj_w = (const float*)d_in[5];
    const float* in_proj_b = (const float*)d_in[6];
    const float* out_w     = (const float*)d_in[7];
    const float* out_b     = (const float*)d_in[8];
    const float* ln1_g     = (const float*)d_in[9];
    const float* ln1_b     = (const float*)d_in[10];
    const float* ln2_g     = (const float*)d_in[11];
    const float* ln2_b     = (const float*)d_in[12];
    const float* fc_w      = (const float*)d_in[13];
    const float* fc_b      = (const float*)d_in[14];
    const float* proj_w    = (const float*)d_in[15];
    const float* proj_b    = (const float*)d_in[16];

    float *ph, *pkv, *pattout, *pt, *pfc, *ppart;
    cudaGetSymbolAddress((void**)&ph,      g_h);
    cudaGetSymbolAddress((void**)&pkv,     g_kv);
    cudaGetSymbolAddress((void**)&pattout, g_attout);
    cudaGetSymbolAddress((void**)&pt,      g_t);
    cudaGetSymbolAddress((void**)&pfc,     g_fc);
    cudaGetSymbolAddress((void**)&ppart,   g_part);

    cudaFuncSetAttribute(gemm_w64<0,0,1>, cudaFuncAttributeMaxDynamicSharedMemorySize, GEMM_SMEM);
    cudaFuncSetAttribute(gemm_w64<0,0,2>, cudaFuncAttributeMaxDynamicSharedMemorySize, GEMM_SMEM);
    cudaFuncSetAttribute(gemm_w64<0,0,4>, cudaFuncAttributeMaxDynamicSharedMemorySize, GEMM_SMEM);
    cudaFuncSetAttribute(gemm_w64<0,0,8>, cudaFuncAttributeMaxDynamicSharedMemorySize, GEMM_SMEM);
    cudaFuncSetAttribute(fused_attn_kernel, cudaFuncAttributeMaxDynamicSharedMemorySize, ATT_SMEM);

    /* 1. LN1 over all tokens (tf32-rounded out) */
    ln1_kernel<<<NROWS, 256>>>(x, ln1_g, ln1_b, ph);

    /* 2. K,V projection: [4616,1024] x [2048,1024]^T */
    gemm_w64<0,0,1><<<dim3(2048/128, (NROWS+127)/128), 128, GEMM_SMEM>>>(
        ph, in_proj_w + 1024*1024, in_proj_b + 1024, pkv, NROWS, 2048, 1024);

    /* 3. fused q proj + attn + softmax + P@V */
    fused_attn_kernel<<<BATCH*NHEAD, 256, ATT_SMEM>>>(mask, in_proj_w, in_proj_b);

    /* 4. output projection (136 rows), split-K 4 -> partials */
    gemm_w64<0,0,4><<<dim3(1024/128, 2, 4), 128, GEMM_SMEM>>>(
        pattout, out_w, out_b, ppart, MROW, 1024, 1024);

    /* 5. residual + out_b + LN2 (reduces 4 partials) */
    resid_ln2_kernel<<<MROW, 256>>>(x, out_b, ln2_g, ln2_b);

    /* 6. MLP fc, split-K 2 -> partials */
    gemm_w64<0,0,2><<<dim3(4096/128, 2, 2), 128, GEMM_SMEM>>>(
        pt, fc_w, fc_b, ppart, MROW, 4096, 1024);

    /* 7. reduce + bias + QuickGELU + tf32 round */
    gelu_reduce_kernel<<<(MROW*4096/4 + 255)/256, 256>>>(fc_b);

    /* 8. MLP proj, split-K 8 -> partials */
    gemm_w64<0,0,8><<<dim3(1024/128, 2, 8), 128, GEMM_SMEM>>>(
        pfc, proj_w, proj_b, ppart, MROW, 1024, 4096);

    /* 9. residual + proj_b + scatter (reduces 8 partials) */
    final_kernel<<<MROW, 256>>>(proj_b, (float*)d_out);
}

// round 8
// speedup vs baseline: 7.7260x; 1.1359x over previous
#include <cuda_runtime.h>
#include <math.h>
#include <stdint.h>

#define S_LEN 577
#define BATCH 8
#define DIM   1024
#define NHEAD 16
#define HD    64
#define NBOX  16
#define NROWS (S_LEN*BATCH)   /* 4616 */
#define MROW  136             /* 128 mask rows + 8 cls rows */

/* ------------------------------------------------------------------ */
/* scratch (device globals; no allocation allowed)                    */
/* ------------------------------------------------------------------ */
__device__ float g_h[NROWS*DIM];          // LN1 output (tf32-rounded)
__device__ float g_kv[NROWS*2048];        // [row, 0:1024]=k, [1024:2048]=v
__device__ float g_attout[MROW*DIM];      // tf32-rounded
__device__ float g_resid[MROW*DIM];
__device__ float g_t[MROW*DIM];           // tf32-rounded
__device__ float g_fc[MROW*4096];         // tf32-rounded
__device__ float g_part[4*MROW*4096];     // split-K partials (= 16*MROW*1024)

/* ------------------------------------------------------------------ */
__device__ __forceinline__ float block_reduce(float v, float* sm, bool is_max) {
    int lane = threadIdx.x & 31, wid = threadIdx.x >> 5;
    #pragma unroll
    for (int o = 16; o; o >>= 1) {
        float u = __shfl_down_sync(0xffffffffu, v, o);
        v = is_max ? fmaxf(v, u) : v + u;
    }
    if (lane == 0) sm[wid] = v;
    __syncthreads();
    int nw = blockDim.x >> 5;
    if (wid == 0) {
        v = (lane < nw) ? sm[lane] : (is_max ? -3.0e38f : 0.0f);
        #pragma unroll
        for (int o = 16; o; o >>= 1) {
            float u = __shfl_down_sync(0xffffffffu, v, o);
            v = is_max ? fmaxf(v, u) : v + u;
        }
        if (lane == 0) sm[0] = v;
    }
    __syncthreads();
    float r = sm[0];
    __syncthreads();
    return r;
}

__device__ __forceinline__ float f2tf32f(float f) {
    uint32_t u;
    asm("cvt.rna.tf32.f32 %0, %1;" : "=r"(u) : "f"(f));
    return __uint_as_float(u);
}

__device__ __forceinline__ void cp_async16(uint32_t saddr, const void* gaddr, int src_size) {
    asm volatile("cp.async.cg.shared.global [%0], [%1], 16, %2;\n"
                 :: "r"(saddr), "l"(gaddr), "r"(src_size));
}

__device__ __forceinline__ uint32_t smem_u32(const void* p) {
    return (uint32_t)__cvta_generic_to_shared(p);
}

/* ------------------------------------------------------------------ */
/* LayerNorm over 1024 cols, one block (256 thr) per row. out tf32.   */
/* ------------------------------------------------------------------ */
__global__ void ln1_kernel(const float* __restrict__ x,
                           const float* __restrict__ g,
                           const float* __restrict__ b,
                           float* __restrict__ out) {
    __shared__ float sred[32];
    int row = blockIdx.x, t = threadIdx.x;
    float4 v = ((const float4*)(x + (size_t)row*DIM))[t];
    float s = v.x + v.y + v.z + v.w;
    s = block_reduce(s, sred, false);
    float mean = s * (1.0f/DIM);
    float dx = v.x-mean, dy = v.y-mean, dz = v.z-mean, dw = v.w-mean;
    float ss = dx*dx + dy*dy + dz*dz + dw*dw;
    ss = block_reduce(ss, sred, false);
    float inv = rsqrtf(ss*(1.0f/DIM) + 1e-5f);
    float4 gv = ((const float4*)g)[t];
    float4 bv = ((const float4*)b)[t];
    float4 o;
    o.x = f2tf32f(dx*inv*gv.x + bv.x);  o.y = f2tf32f(dy*inv*gv.y + bv.y);
    o.z = f2tf32f(dz*inv*gv.z + bv.z);  o.w = f2tf32f(dw*inv*gv.w + bv.w);
    ((float4*)(out + (size_t)row*DIM))[t] = o;
}

/* ------------------------------------------------------------------ */
/* tf32 GEMM: 128 threads, BM=BN=128, BK=32, 4 warps (2x2),           */
/* warp tile 64x64, cp.async double-buffered, 2 CTA/SM.               */
/* SPLITK>1: blockIdx.z = k-chunk; raw partials to C + z*M*N, no bias */
/* ------------------------------------------------------------------ */
#define TSTRIDE 36
#define TILE_F (128*TSTRIDE)
#define GEMM_SMEM (2*2*TILE_F*4)   /* 73728 B */

template<int ACT, int RND, int SPLITK>
__global__ void __launch_bounds__(128, 2)
gemm_w64(const float* __restrict__ A,
         const float* __restrict__ W,
         const float* __restrict__ bias,
         float* __restrict__ C,
         int M, int N, int K) {
    extern __shared__ float smemf[];
    float* Abuf = smemf;                 // [2][128][36]
    float* Bbuf = smemf + 2*TILE_F;      // [2][128][36]
    uint32_t Abase = smem_u32(Abuf);
    uint32_t Bbase = smem_u32(Bbuf);

    int tid = threadIdx.x;
    int warp = tid >> 5, lane = tid & 31;
    int wm = warp & 1, wn = warp >> 1;          // 2 x 2 warps
    int g = lane >> 2, c = lane & 3;
    int m0 = blockIdx.y * 128, n0 = blockIdx.x * 128;
    int Kc = K / SPLITK;
    int kbase = blockIdx.z * Kc;

    float acc[4][8][4];
    #pragma unroll
    for (int i = 0; i < 4; i++)
        #pragma unroll
        for (int j = 0; j < 8; j++)
            #pragma unroll
            for (int r = 0; r < 4; r++) acc[i][j][r] = 0.0f;

    const int NIT = Kc >> 5;

    auto load_tile = [&](int s, int k0) {
        #pragma unroll
        for (int i = 0; i < 8; i++) {
            int ch = tid + i*128;                // 0..1023
            int m = ch >> 3, kq = ch & 7;
            const float* ga = A + (size_t)(m0 + m)*K + k0 + kq*4;
            int sz = (m0 + m < M) ? 16 : 0;
            cp_async16(Abase + (uint32_t)((s*TILE_F + m*TSTRIDE + kq*4)*4), ga, sz);
            const float* gb = W + (size_t)(n0 + m)*K + k0 + kq*4;
            cp_async16(Bbase + (uint32_t)((s*TILE_F + m*TSTRIDE + kq*4)*4), gb, 16);
        }
    };

    load_tile(0, kbase);
    asm volatile("cp.async.commit_group;\n");

    int buf = 0;
    for (int it = 0; it < NIT; it++) {
        if (it + 1 < NIT) load_tile(buf ^ 1, kbase + ((it + 1) << 5));
        asm volatile("cp.async.commit_group;\n");
        asm volatile("cp.async.wait_group 1;\n");
        __syncthreads();

        const float* As_s = Abuf + buf*TILE_F;
        const float* Bs_s = Bbuf + buf*TILE_F;
        #pragma unroll
        for (int kk = 0; kk < 32; kk += 8) {
            uint32_t a[4][4];
            #pragma unroll
            for (int i = 0; i < 4; i++) {
                int mr = (wm*64 + i*16 + g) * TSTRIDE;
                a[i][0] = __float_as_uint(As_s[mr             + kk + c    ]);
                a[i][1] = __float_as_uint(As_s[mr + 8*TSTRIDE + kk + c    ]);
                a[i][2] = __float_as_uint(As_s[mr             + kk + c + 4]);
                a[i][3] = __float_as_uint(As_s[mr + 8*TSTRIDE + kk + c + 4]);
            }
            uint32_t b[8][2];
            #pragma unroll
            for (int j = 0; j < 8; j++) {
                int nc = (wn*64 + j*8 + g) * TSTRIDE;
                b[j][0] = __float_as_uint(Bs_s[nc + kk + c    ]);
                b[j][1] = __float_as_uint(Bs_s[nc + kk + c + 4]);
            }
            #pragma unroll
            for (int i = 0; i < 4; i++)
                #pragma unroll
                for (int j = 0; j < 8; j++) {
                    asm volatile(
                        "mma.sync.aligned.m16n8k8.row.col.f32.tf32.tf32.f32 "
                        "{%0,%1,%2,%3}, {%4,%5,%6,%7}, {%8,%9}, {%0,%1,%2,%3};\n"
                        : "+f"(acc[i][j][0]), "+f"(acc[i][j][1]),
                          "+f"(acc[i][j][2]), "+f"(acc[i][j][3])
                        : "r"(a[i][0]), "r"(a[i][1]), "r"(a[i][2]), "r"(a[i][3]),
                          "r"(b[j][0]), "r"(b[j][1]));
                }
        }
        __syncthreads();
        buf ^= 1;
    }

    float* Co = (SPLITK > 1) ? (C + (size_t)blockIdx.z * M * N) : C;
    #pragma unroll
    for (int i = 0; i < 4; i++) {
        int mA = m0 + wm*64 + i*16 + g;
        int mB = mA + 8;
        #pragma unroll
        for (int j = 0; j < 8; j++) {
            int n = n0 + wn*64 + j*8 + 2*c;
            float b0 = 0.0f, b1 = 0.0f;
            if (SPLITK == 1) { b0 = bias[n]; b1 = bias[n+1]; }
            if (mA < M) {
                float v0 = acc[i][j][0] + b0;
                float v1 = acc[i][j][1] + b1;
                if (ACT == 1) {
                    v0 = v0 / (1.0f + expf(-1.702f * v0));
                    v1 = v1 / (1.0f + expf(-1.702f * v1));
                }
                if (RND == 1) { v0 = f2tf32f(v0); v1 = f2tf32f(v1); }
                *(float2*)(Co + (size_t)mA*N + n) = make_float2(v0, v1);
            }
            if (mB < M) {
                float v0 = acc[i][j][2] + b0;
                float v1 = acc[i][j][3] + b1;
                if (ACT == 1) {
                    v0 = v0 / (1.0f + expf(-1.702f * v0));
                    v1 = v1 / (1.0f + expf(-1.702f * v1));
                }
                if (RND == 1) { v0 = f2tf32f(v0); v1 = f2tf32f(v1); }
                *(float2*)(Co + (size_t)mB*N + n) = make_float2(v0, v1);
            }
        }
    }
}

/* ------------------------------------------------------------------ */
/* Fused attention per (b,h): q proj + attn logits + 17 softmax       */
/* (warp-per-variant, shfl-only reductions) + P@V.  256 threads.      */
/* ------------------------------------------------------------------ */
#define ATT_SMEM (15616*4)

__global__ void fused_attn_kernel(const float* __restrict__ mask,
                                  const float* __restrict__ wq,
                                  const float* __restrict__ bq) {
    extern __shared__ float sm[];
    float* sm_p    = sm;               // 17*577
    float* sm_attn = sm + 9812;        // 577
    float* sm_v    = sm + 10392;       // 64*64
    float* sm_h    = sm + 14528;       // 1024
    float* sm_q    = sm + 15552;       // 64
    int bh = blockIdx.x, b = bh >> 4, h = bh & 15;
    int t = threadIdx.x;               // 256
    int warp = t >> 5, lane = t & 31;

    /* load LN1(x[0,b]) row */
    ((float4*)sm_h)[t] = ((const float4*)(g_h + (size_t)b*DIM))[t];
    __syncthreads();

    /* q projection: warp w computes outputs e = w*8 .. w*8+7 */
    #pragma unroll
    for (int i = 0; i < 8; i++) {
        int e = warp*8 + i;
        const float4* wr = (const float4*)(wq + (size_t)(h*HD + e)*DIM);
        float acc = 0.0f;
        #pragma unroll
        for (int ii = 0; ii < 8; ii++) {
            float4 a = ((const float4*)sm_h)[lane + ii*32];
            float4 w4 = wr[lane + ii*32];
            acc += a.x*w4.x + a.y*w4.y + a.z*w4.z + a.w*w4.w;
        }
        #pragma unroll
        for (int o = 16; o; o >>= 1) acc += __shfl_down_sync(0xffffffffu, acc, o);
        if (lane == 0) sm_q[e] = (acc + bq[h*HD + e]) * 0.125f;
    }
    __syncthreads();

    /* attn logits */
    for (int s = t; s < S_LEN; s += 256) {
        const float4* kr = (const float4*)(g_kv + (size_t)(s*BATCH + b)*2048 + h*HD);
        float acc = 0.0f;
        #pragma unroll
        for (int i = 0; i < 16; i++) {
            float4 kv4 = kr[i];
            acc += kv4.x*sm_q[i*4+0] + kv4.y*sm_q[i*4+1]
                 + kv4.z*sm_q[i*4+2] + kv4.w*sm_q[i*4+3];
        }
        sm_attn[s] = acc;
    }
    __syncthreads();

    /* 17 softmax variants, warp-per-variant, shfl-only reductions */
    for (int var = warp; var < 17; var += 8) {
        float* pr = sm_p + var * S_LEN;
        const float* mrow = (var < 16)
            ? (mask + (size_t)((b*NBOX + var)*NHEAD + h) * S_LEN) : (const float*)0;
        float mx = -3.0e38f;
        for (int s = lane; s < S_LEN; s += 32) {
            float a = sm_attn[s] + (mrow ? __ldg(mrow + s) : 0.0f);
            pr[s] = a;
            mx = fmaxf(mx, a);
        }
        #pragma unroll
        for (int o = 16; o; o >>= 1)
            mx = fmaxf(mx, __shfl_xor_sync(0xffffffffu, mx, o));
        float sum = 0.0f;
        for (int s = lane; s < S_LEN; s += 32) {
            float e = expf(pr[s] - mx);
            pr[s] = e;
            sum += e;
        }
        #pragma unroll
        for (int o = 16; o; o >>= 1)
            sum += __shfl_xor_sync(0xffffffffu, sum, o);
        float inv = 1.0f / sum;
        for (int s = lane; s < S_LEN; s += 32) pr[s] *= inv;
    }
    __syncthreads();

    /* P @ V with V staged through smem */
    int e = t & 63, grp = t >> 6;
    float acc[5] = {0.f, 0.f, 0.f, 0.f, 0.f};
    for (int s0 = 0; s0 < S_LEN; s0 += 64) {
        __syncthreads();
        #pragma unroll
        for (int it = 0; it < 4; it++) {
            int idx = t + it * 256;
            int r = idx >> 4, c4 = (idx & 15) << 2;
            int s = s0 + r;
            float4 vv = make_float4(0.f, 0.f, 0.f, 0.f);
            if (s < S_LEN)
                vv = *(const float4*)(g_kv + (size_t)(s*BATCH + b)*2048 + 1024 + h*HD + c4);
            *(float4*)(sm_v + r*64 + c4) = vv;
        }
        __syncthreads();
        int smax = min(64, S_LEN - s0);
        for (int r = 0; r < smax; r++) {
            float vv = sm_v[r*64 + e];
            #pragma unroll
            for (int i = 0; i < 4; i++)
                acc[i] += sm_p[(grp + 4*i)*S_LEN + s0 + r] * vv;
            if (grp == 0)
                acc[4] += sm_p[16*S_LEN + s0 + r] * vv;
        }
    }
    int col = h*HD + e;
    #pragma unroll
    for (int i = 0; i < 4; i++) {
        int var = grp + 4*i;
        g_attout[(size_t)(b*NBOX + var)*DIM + col] = f2tf32f(acc[i]);
    }
    if (grp == 0)
        g_attout[(size_t)(128 + b)*DIM + col] = f2tf32f(acc[4]);
}

/* ------------------------------------------------------------------ */
/* fc reduce: g_fc = tf32(gelu(sum part0..3 + fc_b)), N=4096          */
/* ------------------------------------------------------------------ */
__global__ void gelu_reduce_kernel(const float* __restrict__ fb) {
    int i = blockIdx.x * blockDim.x + threadIdx.x;   // float4 index
    if (i >= MROW*4096/4) return;
    int n4 = i & (4096/4 - 1);
    float4 bv = ((const float4*)fb)[n4];
    float v[4] = {bv.x, bv.y, bv.z, bv.w};
    #pragma unroll
    for (int z = 0; z < 4; z++) {
        float4 p = ((const float4*)g_part)[(size_t)z*(MROW*4096/4) + i];
        v[0] += p.x; v[1] += p.y; v[2] += p.z; v[3] += p.w;
    }
    float4 o;
    #pragma unroll
    for (int j = 0; j < 4; j++)
        v[j] = f2tf32f(v[j] / (1.0f + expf(-1.702f * v[j])));
    o.x = v[0]; o.y = v[1]; o.z = v[2]; o.w = v[3];
    ((float4*)g_fc)[i] = o;
}

/* ------------------------------------------------------------------ */
/* resid = x0 + (part0..7 + out_b); t = LN2(resid) (tf32-rounded)     */
/* ------------------------------------------------------------------ */
__global__ void resid_ln2_kernel(const float* __restrict__ x,
                                 const float* __restrict__ ob,
                                 const float* __restrict__ g2,
                                 const float* __restrict__ b2) {
    __shared__ float sred[32];
    int m = blockIdx.x, t = threadIdx.x;
    int b = (m < 128) ? (m >> 4) : (m - 128);
    float4 xv = ((const float4*)(x + (size_t)b*DIM))[t];
    float4 bo = ((const float4*)ob)[t];
    float rx = xv.x + bo.x, ry = xv.y + bo.y, rz = xv.z + bo.z, rw = xv.w + bo.w;
    #pragma unroll
    for (int z = 0; z < 8; z++) {
        float4 p = ((const float4*)(g_part + (size_t)(z*MROW + m)*DIM))[t];
        rx += p.x; ry += p.y; rz += p.z; rw += p.w;
    }
    float4 r = make_float4(rx, ry, rz, rw);
    ((float4*)(g_resid + (size_t)m*DIM))[t] = r;
    float s = r.x + r.y + r.z + r.w;
    s = block_reduce(s, sred, false);
    float mean = s * (1.0f/DIM);
    float dx = r.x-mean, dy = r.y-mean, dz = r.z-mean, dw = r.w-mean;
    float ss = dx*dx + dy*dy + dz*dz + dw*dw;
    ss = block_reduce(ss, sred, false);
    float inv = rsqrtf(ss*(1.0f/DIM) + 1e-5f);
    float4 gv = ((const float4*)g2)[t];
    float4 bv = ((const float4*)b2)[t];
    float4 o;
    o.x = f2tf32f(dx*inv*gv.x + bv.x);  o.y = f2tf32f(dy*inv*gv.y + bv.y);
    o.z = f2tf32f(dz*inv*gv.z + bv.z);  o.w = f2tf32f(dw*inv*gv.w + bv.w);
    ((float4*)(g_t + (size_t)m*DIM))[t] = o;
}

/* ------------------------------------------------------------------ */
/* final = resid + (part0..15 + proj_b); scatter to output            */
/* ------------------------------------------------------------------ */
__global__ void final_kernel(const float* __restrict__ pb, float* __restrict__ out) {
    int m = blockIdx.x, t = threadIdx.x;
    float4 r  = ((const float4*)(g_resid + (size_t)m*DIM))[t];
    float4 bv = ((const float4*)pb)[t];
    float ox = r.x + bv.x, oy = r.y + bv.y, oz = r.z + bv.z, ow = r.w + bv.w;
    #pragma unroll
    for (int z = 0; z < 16; z++) {
        float4 p = ((const float4*)(g_part + (size_t)(z*MROW + m)*DIM))[t];
        ox += p.x; oy += p.y; oz += p.z; ow += p.w;
    }
    float4 o = make_float4(ox, oy, oz, ow);
    float* dst = (m < 128) ? (out + (size_t)m*DIM)
                           : (out + 128*DIM + (size_t)(m-128)*DIM);
    ((float4*)dst)[t] = o;
}

/* ------------------------------------------------------------------ */
extern "C" void kernel_launch(void* const* d_in, const int* in_sizes, int n_in,
                              void* d_out, int out_size) {
    const float* x         = (const float*)d_in[0];
    const float* mask      = (const float*)d_in[1];
    const float* in_proj_w = (const float*)d_in[5];
    const float* in_proj_b = (const float*)d_in[6];
    const float* out_w     = (const float*)d_in[7];
    const float* out_b     = (const float*)d_in[8];
    const float* ln1_g     = (const float*)d_in[9];
    const float* ln1_b     = (const float*)d_in[10];
    const float* ln2_g     = (const float*)d_in[11];
    const float* ln2_b     = (const float*)d_in[12];
    const float* fc_w      = (const float*)d_in[13];
    const float* fc_b      = (const float*)d_in[14];
    const float* proj_w    = (const float*)d_in[15];
    const float* proj_b    = (const float*)d_in[16];

    float *ph, *pkv, *pattout, *pt, *pfc, *ppart;
    cudaGetSymbolAddress((void**)&ph,      g_h);
    cudaGetSymbolAddress((void**)&pkv,     g_kv);
    cudaGetSymbolAddress((void**)&pattout, g_attout);
    cudaGetSymbolAddress((void**)&pt,      g_t);
    cudaGetSymbolAddress((void**)&pfc,     g_fc);
    cudaGetSymbolAddress((void**)&ppart,   g_part);

    cudaFuncSetAttribute(gemm_w64<0,0,1>,  cudaFuncAttributeMaxDynamicSharedMemorySize, GEMM_SMEM);
    cudaFuncSetAttribute(gemm_w64<0,0,4>,  cudaFuncAttributeMaxDynamicSharedMemorySize, GEMM_SMEM);
    cudaFuncSetAttribute(gemm_w64<0,0,8>,  cudaFuncAttributeMaxDynamicSharedMemorySize, GEMM_SMEM);
    cudaFuncSetAttribute(gemm_w64<0,0,16>, cudaFuncAttributeMaxDynamicSharedMemorySize, GEMM_SMEM);
    cudaFuncSetAttribute(fused_attn_kernel, cudaFuncAttributeMaxDynamicSharedMemorySize, ATT_SMEM);

    /* 1. LN1 over all tokens (tf32-rounded out) */
    ln1_kernel<<<NROWS, 256>>>(x, ln1_g, ln1_b, ph);

    /* 2. K,V projection: [4616,1024] x [2048,1024]^T */
    gemm_w64<0,0,1><<<dim3(2048/128, (NROWS+127)/128), 128, GEMM_SMEM>>>(
        ph, in_proj_w + 1024*1024, in_proj_b + 1024, pkv, NROWS, 2048, 1024);

    /* 3. fused q proj + attn + softmax + P@V */
    fused_attn_kernel<<<BATCH*NHEAD, 256, ATT_SMEM>>>(mask, in_proj_w, in_proj_b);

    /* 4. output projection (136 rows), split-K 8 -> partials (128 CTAs) */
    gemm_w64<0,0,8><<<dim3(1024/128, 2, 8), 128, GEMM_SMEM>>>(
        pattout, out_w, out_b, ppart, MROW, 1024, 1024);

    /* 5. residual + out_b + LN2 (reduces 8 partials) */
    resid_ln2_kernel<<<MROW, 256>>>(x, out_b, ln2_g, ln2_b);

    /* 6. MLP fc, split-K 4 -> partials (256 CTAs) */
    gemm_w64<0,0,4><<<dim3(4096/128, 2, 4), 128, GEMM_SMEM>>>(
        pt, fc_w, fc_b, ppart, MROW, 4096, 1024);

    /* 7. reduce 4 partials + bias + QuickGELU + tf32 round */
    gelu_reduce_kernel<<<(MROW*4096/4 + 255)/256, 256>>>(fc_b);

    /* 8. MLP proj, split-K 16 -> partials (256 CTAs) */
    gemm_w64<0,0,16><<<dim3(1024/128, 2, 16), 128, GEMM_SMEM>>>(
        pfc, proj_w, proj_b, ppart, MROW, 1024, 4096);

    /* 9. residual + proj_b + scatter (reduces 16 partials) */
    final_kernel<<<MROW, 256>>>(proj_b, (float*)d_out);
}